// round 13
// baseline (speedup 1.0000x reference)
#include <cuda_runtime.h>
#include <math.h>

#define Bb   8
#define Dd   160
#define Nn   32768
#define Kk   589
#define KP   592                 // padded K (float4-aligned, pads are zero)
#define KPR  (KP * 8)            // padded bases/t1 batch stride
#define Rr   8
#define EPSV 1e-6f
#define DN   ((size_t)Dd * (size_t)Nn)
#define KR   (Kk * Rr)           // 4712
#define DR   (Dd * Rr)           // 1280
#define NSLAB 256                // k_xc n-slab (small -> high occupancy)
#define NXBLK 128                // Nn / NSLAB
#define CTS2  260                // ct row stride (floats)

typedef unsigned long long ull;

// ---------------- static device scratch ----------------
__device__ float g_E    [Dd * KP];
__device__ float g_Et   [Kk * Dd];
__device__ float g_EtE  [(size_t)Kk * KP];
__device__ float g_bases[Bb * KPR];
__device__ float g_t1   [Bb * KPR];
__device__ float g_ebp  [2 * Bb * DR];              // Eb split-K partials
__device__ float g_coef [(size_t)Bb * Nn * Rr];
__device__ float g_sxc  [(size_t)Bb * NXBLK * DR];
__device__ float g_sctc [(size_t)Bb * NXBLK * 256]; // quarter-slab ctc partials
__device__ float g_xcoef[Bb * DR];

// ---------------- packed f32x2 helpers ----------------
__device__ __forceinline__ ull pk2(float lo, float hi) {
    ull r;
    asm("mov.b64 %0, {%1, %2};" : "=l"(r) : "f"(lo), "f"(hi));
    return r;
}
__device__ __forceinline__ void upk2(ull v, float& lo, float& hi) {
    asm("mov.b64 {%0, %1}, %2;" : "=f"(lo), "=f"(hi) : "l"(v));
}
__device__ __forceinline__ ull fma2_(ull a, ull b, ull c) {
    ull d;
    asm("fma.rn.f32x2 %0, %1, %2, %3;" : "=l"(d) : "l"(a), "l"(b), "l"(c));
    return d;
}

// ---------------- init: build E (+T) and L2-normalize bases, one kernel ----------------
__global__ void k_init(const float* __restrict__ bin) {
    if (blockIdx.x < Dd) {
        int d = blockIdx.x;
        for (int k = threadIdx.x; k < KP; k += blockDim.x) {
            float v = 0.f;
            if (k < Kk) {
                if (k == 588) {
                    v = 1.0f;
                } else {
                    float sig; int n;
                    if      (k < 160) { sig = 6.0f;  n = k; }
                    else if (k < 320) { sig = 8.0f;  n = k - 160; }
                    else if (k < 400) { sig = 12.0f; n = (k - 320) * 2; }
                    else if (k < 480) { sig = 15.0f; n = (k - 400) * 2; }
                    else if (k < 534) { sig = 18.0f; n = (k - 480) * 3; }
                    else              { sig = 24.0f; n = (k - 534) * 3; }
                    float diff = (float)d - (float)n;
                    v = expf(-0.5f * (diff * diff) / (2.0f * sig * sig));
                }
            }
            g_E[d * KP + k] = v;
            if (k < Kk) g_Et[k * Dd + d] = v;
        }
    } else {
        int b = blockIdx.x - Dd;
        int r = threadIdx.x >> 5;
        int l = threadIdx.x & 31;
        float ss = 0.f;
        for (int k = l; k < Kk; k += 32) {
            float v = bin[(b * Kk + k) * Rr + r];
            ss += v * v;
        }
        #pragma unroll
        for (int o = 16; o; o >>= 1) ss += __shfl_xor_sync(0xffffffffu, ss, o);
        float nrm = fmaxf(sqrtf(ss), 1e-12f);
        for (int k = l; k < Kk; k += 32)
            g_bases[b * KPR + k * Rr + r] = bin[(b * Kk + k) * Rr + r] / nrm;
        if (threadIdx.x < KPR - KR)
            g_bases[b * KPR + KR + threadIdx.x] = 0.f;
    }
}

// ---------------- EtE = E^T E : grid(148), 4 rows/block ----------------
__global__ __launch_bounds__(256) void k_EtE() {
    __shared__ float se[Dd * 4];
    int i0 = blockIdx.x * 4;
    int t = threadIdx.x;
    for (int idx = t; idx < Dd * 4; idx += 256) {
        int d = idx >> 2, i = idx & 3;
        int ki = i0 + i;
        se[idx] = (ki < Kk) ? g_Et[ki * Dd + d] : 0.f;
    }
    __syncthreads();
    int j0 = t, j1 = t + 256, j2 = t + 512;
    bool has2 = (j2 < KP);
    float a0[4] = {0,0,0,0}, a1[4] = {0,0,0,0}, a2[4] = {0,0,0,0};
    #pragma unroll 4
    for (int d = 0; d < Dd; d++) {
        float e0 = g_E[d * KP + j0];
        float e1 = g_E[d * KP + j1];
        float e2 = has2 ? g_E[d * KP + j2] : 0.f;
        #pragma unroll
        for (int i = 0; i < 4; i++) {
            float s = se[d * 4 + i];
            a0[i] = fmaf(e0, s, a0[i]);
            a1[i] = fmaf(e1, s, a1[i]);
            a2[i] = fmaf(e2, s, a2[i]);
        }
    }
    #pragma unroll
    for (int i = 0; i < 4; i++) {
        int row = i0 + i;
        if (row < Kk) {
            g_EtE[(size_t)row * KP + j0] = a0[i];
            g_EtE[(size_t)row * KP + j1] = a1[i];
            if (has2) g_EtE[(size_t)row * KP + j2] = a2[i];
        }
    }
}

// ---------------- Eb partials: grid(40, 2, Bb), 8 lanes per output ----------------
__global__ __launch_bounds__(256) void k_EbG2() {
    int t = threadIdx.x;
    int q = blockIdx.y, b = blockIdx.z;
    int out = t >> 3, kg = t & 7;
    int idx = blockIdx.x * 32 + out;               // 0..1279
    int d = idx >> 3, r = idx & 7;
    const float* Erow = g_E + d * KP + q * 296 + kg;
    const float* brow = g_bases + b * KPR + (q * 296 + kg) * 8 + r;
    float acc0 = 0.f, acc1 = 0.f;
    #pragma unroll
    for (int i = 0; i < 36; i += 2) {
        acc0 = fmaf(Erow[8 * i],       brow[64 * i],       acc0);
        acc1 = fmaf(Erow[8 * (i + 1)], brow[64 * (i + 1)], acc1);
    }
    acc0 = fmaf(Erow[8 * 36], brow[64 * 36], acc0);
    float acc = acc0 + acc1;
    acc += __shfl_down_sync(0xffffffffu, acc, 4);
    acc += __shfl_down_sync(0xffffffffu, acc, 2);
    acc += __shfl_down_sync(0xffffffffu, acc, 1);
    if (kg == 0) g_ebp[(q * Bb + b) * DR + idx] = acc;
}

// ---------------- k_num: streaming coef update, 2 columns/thread ----------------
template<int INIT>
__global__ __launch_bounds__(256) void k_num(const float* __restrict__ x) {
    __shared__ __align__(16) ull ebs2[Dd * Rr];    // (e,e) duplicated pairs, 10.2 KB
    __shared__ ull gs2[64];
    int t = threadIdx.x, blk = blockIdx.x, b = blockIdx.y;
    int n0 = blk * 512;
    for (int i = t; i < DR; i += 256) {
        float v = g_ebp[b * DR + i] + g_ebp[(Bb + b) * DR + i];
        ebs2[i] = pk2(v, v);
    }
    __syncthreads();
    if (t < 64) {
        int r = t >> 3, s = t & 7;
        const float* ef = (const float*)ebs2;
        float a = 0.f;
        #pragma unroll 8
        for (int d = 0; d < Dd; d++)
            a = fmaf(ef[(d * 8 + r) * 2], ef[(d * 8 + s) * 2], a);
        gs2[t] = pk2(a, a);
    }

    const float* xb = x + (size_t)b * DN + n0 + 2 * t;
    ull L2a[8] = {0,0,0,0,0,0,0,0};
    #pragma unroll 1
    for (int d0 = 0; d0 < Dd; d0 += 16) {
        float2 xv[16];
        #pragma unroll
        for (int i = 0; i < 16; i++) xv[i] = *(const float2*)(xb + (size_t)(d0 + i) * Nn);
        #pragma unroll
        for (int i = 0; i < 16; i++) {
            ull x2 = pk2(xv[i].x, xv[i].y);
            const ulonglong2* ep = (const ulonglong2*)(ebs2 + (d0 + i) * 8);
            ulonglong2 e0 = ep[0], e1 = ep[1], e2 = ep[2], e3 = ep[3];
            L2a[0] = fma2_(x2, e0.x, L2a[0]);
            L2a[1] = fma2_(x2, e0.y, L2a[1]);
            L2a[2] = fma2_(x2, e1.x, L2a[2]);
            L2a[3] = fma2_(x2, e1.y, L2a[3]);
            L2a[4] = fma2_(x2, e2.x, L2a[4]);
            L2a[5] = fma2_(x2, e2.y, L2a[5]);
            L2a[6] = fma2_(x2, e3.x, L2a[6]);
            L2a[7] = fma2_(x2, e3.y, L2a[7]);
        }
    }
    __syncthreads();   // gs2 visible

    float L0[8], L1[8];
    #pragma unroll
    for (int r = 0; r < 8; r++) upk2(L2a[r], L0[r], L1[r]);

    size_t cbase = ((size_t)b * Nn + n0 + 2 * t) * 8;
    float c0[8], c1c[8];
    if (INIT) {
        float m0 = L0[0], m1 = L1[0];
        #pragma unroll
        for (int i = 1; i < 8; i++) { m0 = fmaxf(m0, L0[i]); m1 = fmaxf(m1, L1[i]); }
        float p0 = 0.f, p1 = 0.f;
        #pragma unroll
        for (int i = 0; i < 8; i++) {
            c0[i] = expf(L0[i] - m0); p0 += c0[i];
            c1c[i] = expf(L1[i] - m1); p1 += c1c[i];
        }
        float i0 = 1.0f / p0, i1 = 1.0f / p1;
        #pragma unroll
        for (int i = 0; i < 8; i++) { c0[i] *= i0; c1c[i] *= i1; }
    } else {
        const float4* cg = (const float4*)(g_coef + cbase);
        float4 a = cg[0], cA = cg[1], d = cg[2], e = cg[3];
        c0[0]=a.x; c0[1]=a.y; c0[2]=a.z; c0[3]=a.w;
        c0[4]=cA.x; c0[5]=cA.y; c0[6]=cA.z; c0[7]=cA.w;
        c1c[0]=d.x; c1c[1]=d.y; c1c[2]=d.z; c1c[3]=d.w;
        c1c[4]=e.x; c1c[5]=e.y; c1c[6]=e.z; c1c[7]=e.w;
    }

    ull cpk[8];
    #pragma unroll
    for (int s = 0; s < 8; s++) cpk[s] = pk2(c0[s], c1c[s]);
    float o0[8], o1[8];
    #pragma unroll
    for (int r = 0; r < 8; r++) {
        ull den2 = 0ull;
        #pragma unroll
        for (int s = 0; s < 8; s++) den2 = fma2_(cpk[s], gs2[s * 8 + r], den2);
        float dn0, dn1; upk2(den2, dn0, dn1);
        o0[r] = c0[r] * L0[r] / (dn0 + EPSV);
        o1[r] = c1c[r] * L1[r] / (dn1 + EPSV);
    }
    float4* cgw = (float4*)(g_coef + cbase);
    cgw[0] = make_float4(o0[0], o0[1], o0[2], o0[3]);
    cgw[1] = make_float4(o0[4], o0[5], o0[6], o0[7]);
    cgw[2] = make_float4(o1[0], o1[1], o1[2], o1[3]);
    cgw[3] = make_float4(o1[4], o1[5], o1[6], o1[7]);
}

// ---------------- k_xc: x@coef + ctc partials over 256-n slab (6 CTAs/SM) ----------------
__global__ __launch_bounds__(256, 6) void k_xc(const float* __restrict__ x) {
    __shared__ __align__(16) float ct[Rr * CTS2];   // 8.3 KB
    int t = threadIdx.x, blk = blockIdx.x, b = blockIdx.y;
    int n0 = blk * NSLAB;

    {
        int nn = t;
        const float4* cg = (const float4*)(g_coef + ((size_t)b * Nn + n0 + nn) * 8);
        float4 a = cg[0], c = cg[1];
        ct[0*CTS2+nn]=a.x; ct[1*CTS2+nn]=a.y; ct[2*CTS2+nn]=a.z; ct[3*CTS2+nn]=a.w;
        ct[4*CTS2+nn]=c.x; ct[5*CTS2+nn]=c.y; ct[6*CTS2+nn]=c.z; ct[7*CTS2+nn]=c.w;
    }
    __syncthreads();

    int p  = t & 3;                  // r-pair: r = 2p, 2p+1
    int dq = t >> 2;                 // 0..63
    bool has2 = (dq < 32);           // warp-uniform
    const float* xb  = x + (size_t)b * DN + n0;
    const float* xr0 = xb + (size_t)dq * Nn;
    const float* xr1 = xb + (size_t)(dq + 64) * Nn;
    const float* xr2 = xb + (size_t)(has2 ? dq + 128 : dq) * Nn;
    const ull* c0p = (const ull*)(ct + (2 * p)     * CTS2);
    const ull* c1p = (const ull*)(ct + (2 * p + 1) * CTS2);

    ull aA0=0,aB0=0,aA1=0,aB1=0,aA2=0,aB2=0;
    #pragma unroll 4
    for (int n4 = 0; n4 < NSLAB / 4; n4++) {
        ulonglong2 c0  = *(const ulonglong2*)(c0p + n4 * 2);
        ulonglong2 c1v = *(const ulonglong2*)(c1p + n4 * 2);
        ulonglong2 x0  = *(const ulonglong2*)(xr0 + n4 * 4);
        ulonglong2 x1  = *(const ulonglong2*)(xr1 + n4 * 4);
        aA0 = fma2_(x0.x, c0.x,  aA0); aA0 = fma2_(x0.y, c0.y,  aA0);
        aB0 = fma2_(x0.x, c1v.x, aB0); aB0 = fma2_(x0.y, c1v.y, aB0);
        aA1 = fma2_(x1.x, c0.x,  aA1); aA1 = fma2_(x1.y, c0.y,  aA1);
        aB1 = fma2_(x1.x, c1v.x, aB1); aB1 = fma2_(x1.y, c1v.y, aB1);
        if (has2) {
            ulonglong2 x2 = *(const ulonglong2*)(xr2 + n4 * 4);
            aA2 = fma2_(x2.x, c0.x,  aA2); aA2 = fma2_(x2.y, c0.y,  aA2);
            aB2 = fma2_(x2.x, c1v.x, aB2); aB2 = fma2_(x2.y, c1v.y, aB2);
        }
    }
    float* outp = g_sxc + (size_t)(b * NXBLK + blk) * DR;
    {
        float la, ha, lb, hb;
        upk2(aA0, la, ha); upk2(aB0, lb, hb);
        *(float2*)(outp + dq * 8 + 2 * p) = make_float2(la + ha, lb + hb);
        upk2(aA1, la, ha); upk2(aB1, lb, hb);
        *(float2*)(outp + (dq + 64) * 8 + 2 * p) = make_float2(la + ha, lb + hb);
        if (has2) {
            upk2(aA2, la, ha); upk2(aB2, lb, hb);
            *(float2*)(outp + (dq + 128) * 8 + 2 * p) = make_float2(la + ha, lb + hb);
        }
    }

    // ctc quarter-slab partials: all 256 threads, 16 iterations each
    {
        int rs = t & 63, q = t >> 6;
        int r = rs >> 3, s = rs & 7;
        const ull* rp = (const ull*)(ct + r * CTS2 + q * 64);
        const ull* sp = (const ull*)(ct + s * CTS2 + q * 64);
        ull a2 = 0ull, b2 = 0ull;
        #pragma unroll
        for (int i = 0; i < 16; i++) {
            a2 = fma2_(rp[2 * i],     sp[2 * i],     a2);
            b2 = fma2_(rp[2 * i + 1], sp[2 * i + 1], b2);
        }
        float lo, hi, lo2, hi2;
        upk2(a2, lo, hi); upk2(b2, lo2, hi2);
        g_sctc[(size_t)(b * NXBLK + blk) * 256 + t] = (lo + hi) + (lo2 + hi2);
    }
}

// ---------------- glue A: grid(6,B). bx<5: reduce x@coef; bx==5: ctc + t1 ----------------
__global__ void k_glueA() {
    __shared__ float sc[64];
    __shared__ float spart[256];
    int bx = blockIdx.x, b = blockIdx.y, t = threadIdx.x;
    if (bx < 5) {
        int o = bx * 256 + t;
        const float* p = g_sxc + (size_t)b * NXBLK * DR + o;
        float a0 = 0, a1 = 0, a2 = 0, a3 = 0;
        #pragma unroll 2
        for (int blk = 0; blk < NXBLK; blk += 4) {
            a0 += p[(size_t)(blk + 0) * DR];
            a1 += p[(size_t)(blk + 1) * DR];
            a2 += p[(size_t)(blk + 2) * DR];
            a3 += p[(size_t)(blk + 3) * DR];
        }
        g_xcoef[b * DR + o] = (a0 + a1) + (a2 + a3);
        return;
    }
    {
        // reduce ctc quarter partials: thread (o = t&63, q = t>>6)
        int o = t & 63, q = t >> 6;
        const float* p = g_sctc + (size_t)b * NXBLK * 256 + q * 64 + o;
        float acc = 0.f;
        #pragma unroll 4
        for (int blk = 0; blk < NXBLK; blk++) acc += p[(size_t)blk * 256];
        spart[t] = acc;
    }
    __syncthreads();
    if (t < 64) sc[t] = (spart[t] + spart[t + 64]) + (spart[t + 128] + spart[t + 192]);
    __syncthreads();
    const float* bs = g_bases + b * KPR;
    float* t1 = g_t1 + b * KPR;
    for (int idx = t; idx < KR; idx += 256) {
        int k = idx >> 3, r = idx & 7;
        float a = 0.f;
        #pragma unroll
        for (int s = 0; s < 8; s++) a = fmaf(bs[k * 8 + s], sc[s * 8 + r], a);
        t1[idx] = a;
    }
}

// ---------------- glue B: bases *= (E^T xcoef) / (EtE @ t1 + eps) ----------------
__global__ __launch_bounds__(256) void k_glueB() {
    __shared__ float sx[DR];
    __shared__ __align__(16) float st1[KP * Rr];
    int b = blockIdx.y, t = threadIdx.x;
    for (int i = t; i < DR; i += 256) sx[i] = g_xcoef[b * DR + i];
    for (int i = t; i < KP * Rr; i += 256) st1[i] = g_t1[b * KPR + i];
    __syncthreads();
    int idx = blockIdx.x * 256 + t;
    if (idx >= KR) return;
    int k = idx >> 3, r = idx & 7;
    const float4* et = (const float4*)(g_Et + k * Dd);
    float n0 = 0.f, n1 = 0.f, n2 = 0.f, n3 = 0.f;
    #pragma unroll 8
    for (int i = 0; i < Dd / 4; i++) {
        float4 e = et[i];
        n0 = fmaf(e.x, sx[(4 * i + 0) * 8 + r], n0);
        n1 = fmaf(e.y, sx[(4 * i + 1) * 8 + r], n1);
        n2 = fmaf(e.z, sx[(4 * i + 2) * 8 + r], n2);
        n3 = fmaf(e.w, sx[(4 * i + 3) * 8 + r], n3);
    }
    float num = (n0 + n1) + (n2 + n3);
    const float4* ee = (const float4*)(g_EtE + (size_t)k * KP);
    float d0 = 0.f, d1 = 0.f, d2 = 0.f, d3 = 0.f;
    #pragma unroll 8
    for (int i = 0; i < KP / 4; i++) {
        float4 v = ee[i];
        d0 = fmaf(v.x, st1[(4 * i + 0) * 8 + r], d0);
        d1 = fmaf(v.y, st1[(4 * i + 1) * 8 + r], d1);
        d2 = fmaf(v.z, st1[(4 * i + 2) * 8 + r], d2);
        d3 = fmaf(v.w, st1[(4 * i + 3) * 8 + r], d3);
    }
    float den = (d0 + d1) + (d2 + d3);
    g_bases[b * KPR + idx] *= num / (den + EPSV);
}

// ---------------- final coef update + reconstruction, 2 columns/thread ----------------
__global__ __launch_bounds__(256) void k_final(const float* __restrict__ x,
                                               float* __restrict__ out) {
    __shared__ __align__(16) ull ebs2[Dd * Rr];
    __shared__ ull gs2[64];
    int t = threadIdx.x, blk = blockIdx.x, b = blockIdx.y;
    int n0 = blk * 512;
    for (int i = t; i < DR; i += 256) {
        float v = g_ebp[b * DR + i] + g_ebp[(Bb + b) * DR + i];
        ebs2[i] = pk2(v, v);
    }
    __syncthreads();
    if (t < 64) {
        int r = t >> 3, s = t & 7;
        const float* ef = (const float*)ebs2;
        float a = 0.f;
        #pragma unroll 8
        for (int d = 0; d < Dd; d++)
            a = fmaf(ef[(d * 8 + r) * 2], ef[(d * 8 + s) * 2], a);
        gs2[t] = pk2(a, a);
    }

    const float* xb = x + (size_t)b * DN + n0 + 2 * t;
    ull L2a[8] = {0,0,0,0,0,0,0,0};
    #pragma unroll 1
    for (int d0 = 0; d0 < Dd; d0 += 16) {
        float2 xv[16];
        #pragma unroll
        for (int i = 0; i < 16; i++) xv[i] = *(const float2*)(xb + (size_t)(d0 + i) * Nn);
        #pragma unroll
        for (int i = 0; i < 16; i++) {
            ull x2 = pk2(xv[i].x, xv[i].y);
            const ulonglong2* ep = (const ulonglong2*)(ebs2 + (d0 + i) * 8);
            ulonglong2 e0 = ep[0], e1 = ep[1], e2 = ep[2], e3 = ep[3];
            L2a[0] = fma2_(x2, e0.x, L2a[0]);
            L2a[1] = fma2_(x2, e0.y, L2a[1]);
            L2a[2] = fma2_(x2, e1.x, L2a[2]);
            L2a[3] = fma2_(x2, e1.y, L2a[3]);
            L2a[4] = fma2_(x2, e2.x, L2a[4]);
            L2a[5] = fma2_(x2, e2.y, L2a[5]);
            L2a[6] = fma2_(x2, e3.x, L2a[6]);
            L2a[7] = fma2_(x2, e3.y, L2a[7]);
        }
    }
    __syncthreads();

    float L0[8], L1[8];
    #pragma unroll
    for (int r = 0; r < 8; r++) upk2(L2a[r], L0[r], L1[r]);

    size_t cbase = ((size_t)b * Nn + n0 + 2 * t) * 8;
    const float4* cg = (const float4*)(g_coef + cbase);
    float4 a = cg[0], cA = cg[1], dV = cg[2], eV = cg[3];
    float c0[8] = {a.x, a.y, a.z, a.w, cA.x, cA.y, cA.z, cA.w};
    float c1c[8] = {dV.x, dV.y, dV.z, dV.w, eV.x, eV.y, eV.z, eV.w};

    ull cpk[8];
    #pragma unroll
    for (int s = 0; s < 8; s++) cpk[s] = pk2(c0[s], c1c[s]);
    ull c1pk[8];
    #pragma unroll
    for (int r = 0; r < 8; r++) {
        ull den2 = 0ull;
        #pragma unroll
        for (int s = 0; s < 8; s++) den2 = fma2_(cpk[s], gs2[s * 8 + r], den2);
        float dn0, dn1; upk2(den2, dn0, dn1);
        float v0 = c0[r] * L0[r] / (dn0 + EPSV);
        float v1 = c1c[r] * L1[r] / (dn1 + EPSV);
        c1pk[r] = pk2(v0, v1);
    }

    float* ob = out + (size_t)b * DN + n0 + 2 * t;
    #pragma unroll 4
    for (int d = 0; d < Dd; d++) {
        const ulonglong2* ep = (const ulonglong2*)(ebs2 + d * 8);
        ulonglong2 e0 = ep[0], e1 = ep[1], e2 = ep[2], e3 = ep[3];
        ull acc = 0ull;
        acc = fma2_(e0.x, c1pk[0], acc);
        acc = fma2_(e0.y, c1pk[1], acc);
        acc = fma2_(e1.x, c1pk[2], acc);
        acc = fma2_(e1.y, c1pk[3], acc);
        acc = fma2_(e2.x, c1pk[4], acc);
        acc = fma2_(e2.y, c1pk[5], acc);
        acc = fma2_(e3.x, c1pk[6], acc);
        acc = fma2_(e3.y, c1pk[7], acc);
        float lo, hi; upk2(acc, lo, hi);
        *(float2*)(ob + (size_t)d * Nn) = make_float2(lo, hi);
    }
}

// ---------------- launch ----------------
extern "C" void kernel_launch(void* const* d_in, const int* in_sizes, int n_in,
                              void* d_out, int out_size) {
    const float* x = (const float*)d_in[0];
    const float* binit = (const float*)d_in[1];
    float* out = (float*)d_out;

    k_init<<<Dd + Bb, 256>>>(binit);                 // 0
    k_EbG2<<<dim3(40, 2, Bb), 256>>>();              // 1
    k_num<1><<<dim3(Nn / 512, Bb), 256>>>(x);        // 2
    k_xc<<<dim3(NXBLK, Bb), 256>>>(x);               // 3  <- profiled
    k_EtE<<<148, 256>>>();                           // 4
    k_glueA<<<dim3(6, Bb), 256>>>();
    k_glueB<<<dim3(19, Bb), 256>>>();
    k_EbG2<<<dim3(40, 2, Bb), 256>>>();

    for (int s = 1; s < 4; s++) {
        k_num<0><<<dim3(Nn / 512, Bb), 256>>>(x);
        k_xc<<<dim3(NXBLK, Bb), 256>>>(x);
        k_glueA<<<dim3(6, Bb), 256>>>();
        k_glueB<<<dim3(19, Bb), 256>>>();
        k_EbG2<<<dim3(40, 2, Bb), 256>>>();
    }
    k_final<<<dim3(Nn / 512, Bb), 256>>>(x, out);
}

// round 14
// speedup vs baseline: 1.0733x; 1.0733x over previous
#include <cuda_runtime.h>
#include <math.h>

#define Bb   8
#define Dd   160
#define Nn   32768
#define Kk   589
#define KP   592                 // padded K (float4-aligned, pads are zero)
#define KPR  (KP * 8)            // padded bases/t1 batch stride
#define Rr   8
#define EPSV 1e-6f
#define DN   ((size_t)Dd * (size_t)Nn)
#define KR   (Kk * Rr)           // 4712
#define DR   (Dd * Rr)           // 1280
#define NSLAB 256                // k_xc n-slab (small -> high occupancy)
#define NXBLK 128                // Nn / NSLAB
#define CTS2  260                // ct row stride (floats)

typedef unsigned long long ull;

// ---------------- static device scratch ----------------
__device__ float g_E    [Dd * KP];
__device__ float g_Et   [Kk * Dd];
__device__ float g_EtE  [(size_t)Kk * KP];
__device__ float g_bases[Bb * KPR];
__device__ float g_t1   [Bb * KPR];
__device__ float g_ebp  [2 * Bb * DR];              // Eb split-K partials
__device__ float g_coef [(size_t)Bb * Nn * Rr];
__device__ float g_sxc  [(size_t)Bb * NXBLK * DR];
__device__ float g_sctc [Bb * NXBLK * 64];
__device__ float g_xcoef[Bb * DR];

// ---------------- packed f32x2 helpers ----------------
__device__ __forceinline__ ull pk2(float lo, float hi) {
    ull r;
    asm("mov.b64 %0, {%1, %2};" : "=l"(r) : "f"(lo), "f"(hi));
    return r;
}
__device__ __forceinline__ void upk2(ull v, float& lo, float& hi) {
    asm("mov.b64 {%0, %1}, %2;" : "=f"(lo), "=f"(hi) : "l"(v));
}
__device__ __forceinline__ ull fma2_(ull a, ull b, ull c) {
    ull d;
    asm("fma.rn.f32x2 %0, %1, %2, %3;" : "=l"(d) : "l"(a), "l"(b), "l"(c));
    return d;
}

// ---------------- init: build E (+T) and L2-normalize bases, one kernel ----------------
__global__ void k_init(const float* __restrict__ bin) {
    if (blockIdx.x < Dd) {
        int d = blockIdx.x;
        for (int k = threadIdx.x; k < KP; k += blockDim.x) {
            float v = 0.f;
            if (k < Kk) {
                if (k == 588) {
                    v = 1.0f;
                } else {
                    float sig; int n;
                    if      (k < 160) { sig = 6.0f;  n = k; }
                    else if (k < 320) { sig = 8.0f;  n = k - 160; }
                    else if (k < 400) { sig = 12.0f; n = (k - 320) * 2; }
                    else if (k < 480) { sig = 15.0f; n = (k - 400) * 2; }
                    else if (k < 534) { sig = 18.0f; n = (k - 480) * 3; }
                    else              { sig = 24.0f; n = (k - 534) * 3; }
                    float diff = (float)d - (float)n;
                    v = expf(-0.5f * (diff * diff) / (2.0f * sig * sig));
                }
            }
            g_E[d * KP + k] = v;
            if (k < Kk) g_Et[k * Dd + d] = v;
        }
    } else {
        int b = blockIdx.x - Dd;
        int r = threadIdx.x >> 5;
        int l = threadIdx.x & 31;
        float ss = 0.f;
        for (int k = l; k < Kk; k += 32) {
            float v = bin[(b * Kk + k) * Rr + r];
            ss += v * v;
        }
        #pragma unroll
        for (int o = 16; o; o >>= 1) ss += __shfl_xor_sync(0xffffffffu, ss, o);
        float nrm = fmaxf(sqrtf(ss), 1e-12f);
        for (int k = l; k < Kk; k += 32)
            g_bases[b * KPR + k * Rr + r] = bin[(b * Kk + k) * Rr + r] / nrm;
        if (threadIdx.x < KPR - KR)
            g_bases[b * KPR + KR + threadIdx.x] = 0.f;
    }
}

// ---------------- EtE = E^T E : grid(148), 4 rows/block ----------------
__global__ __launch_bounds__(256) void k_EtE() {
    __shared__ float se[Dd * 4];
    int i0 = blockIdx.x * 4;
    int t = threadIdx.x;
    for (int idx = t; idx < Dd * 4; idx += 256) {
        int d = idx >> 2, i = idx & 3;
        int ki = i0 + i;
        se[idx] = (ki < Kk) ? g_Et[ki * Dd + d] : 0.f;
    }
    __syncthreads();
    int j0 = t, j1 = t + 256, j2 = t + 512;
    bool has2 = (j2 < KP);
    float a0[4] = {0,0,0,0}, a1[4] = {0,0,0,0}, a2[4] = {0,0,0,0};
    #pragma unroll 4
    for (int d = 0; d < Dd; d++) {
        float e0 = g_E[d * KP + j0];
        float e1 = g_E[d * KP + j1];
        float e2 = has2 ? g_E[d * KP + j2] : 0.f;
        #pragma unroll
        for (int i = 0; i < 4; i++) {
            float s = se[d * 4 + i];
            a0[i] = fmaf(e0, s, a0[i]);
            a1[i] = fmaf(e1, s, a1[i]);
            a2[i] = fmaf(e2, s, a2[i]);
        }
    }
    #pragma unroll
    for (int i = 0; i < 4; i++) {
        int row = i0 + i;
        if (row < Kk) {
            g_EtE[(size_t)row * KP + j0] = a0[i];
            g_EtE[(size_t)row * KP + j1] = a1[i];
            if (has2) g_EtE[(size_t)row * KP + j2] = a2[i];
        }
    }
}

// ---------------- Eb partials: grid(40, 2, Bb), 8 lanes per output ----------------
__global__ __launch_bounds__(256) void k_EbG2() {
    int t = threadIdx.x;
    int q = blockIdx.y, b = blockIdx.z;
    int out = t >> 3, kg = t & 7;
    int idx = blockIdx.x * 32 + out;               // 0..1279
    int d = idx >> 3, r = idx & 7;
    const float* Erow = g_E + d * KP + q * 296 + kg;
    const float* brow = g_bases + b * KPR + (q * 296 + kg) * 8 + r;
    float acc0 = 0.f, acc1 = 0.f;
    #pragma unroll
    for (int i = 0; i < 36; i += 2) {
        acc0 = fmaf(Erow[8 * i],       brow[64 * i],       acc0);
        acc1 = fmaf(Erow[8 * (i + 1)], brow[64 * (i + 1)], acc1);
    }
    acc0 = fmaf(Erow[8 * 36], brow[64 * 36], acc0);
    float acc = acc0 + acc1;
    acc += __shfl_down_sync(0xffffffffu, acc, 4);
    acc += __shfl_down_sync(0xffffffffu, acc, 2);
    acc += __shfl_down_sync(0xffffffffu, acc, 1);
    if (kg == 0) g_ebp[(q * Bb + b) * DR + idx] = acc;
}

// ---------------- k_num: streaming coef update, 2 columns/thread ----------------
template<int INIT>
__global__ __launch_bounds__(256) void k_num(const float* __restrict__ x) {
    __shared__ __align__(16) ull ebs2[Dd * Rr];    // (e,e) duplicated pairs, 10.2 KB
    __shared__ ull gs2[64];
    int t = threadIdx.x, blk = blockIdx.x, b = blockIdx.y;
    int n0 = blk * 512;
    for (int i = t; i < DR; i += 256) {
        float v = g_ebp[b * DR + i] + g_ebp[(Bb + b) * DR + i];
        ebs2[i] = pk2(v, v);
    }
    __syncthreads();
    if (t < 64) {
        int r = t >> 3, s = t & 7;
        const float* ef = (const float*)ebs2;
        float a = 0.f;
        #pragma unroll 8
        for (int d = 0; d < Dd; d++)
            a = fmaf(ef[(d * 8 + r) * 2], ef[(d * 8 + s) * 2], a);
        gs2[t] = pk2(a, a);
    }

    const float* xb = x + (size_t)b * DN + n0 + 2 * t;
    ull L2a[8] = {0,0,0,0,0,0,0,0};
    #pragma unroll 1
    for (int d0 = 0; d0 < Dd; d0 += 16) {
        float2 xv[16];
        #pragma unroll
        for (int i = 0; i < 16; i++) xv[i] = *(const float2*)(xb + (size_t)(d0 + i) * Nn);
        #pragma unroll
        for (int i = 0; i < 16; i++) {
            ull x2 = pk2(xv[i].x, xv[i].y);
            const ulonglong2* ep = (const ulonglong2*)(ebs2 + (d0 + i) * 8);
            ulonglong2 e0 = ep[0], e1 = ep[1], e2 = ep[2], e3 = ep[3];
            L2a[0] = fma2_(x2, e0.x, L2a[0]);
            L2a[1] = fma2_(x2, e0.y, L2a[1]);
            L2a[2] = fma2_(x2, e1.x, L2a[2]);
            L2a[3] = fma2_(x2, e1.y, L2a[3]);
            L2a[4] = fma2_(x2, e2.x, L2a[4]);
            L2a[5] = fma2_(x2, e2.y, L2a[5]);
            L2a[6] = fma2_(x2, e3.x, L2a[6]);
            L2a[7] = fma2_(x2, e3.y, L2a[7]);
        }
    }
    __syncthreads();   // gs2 visible

    float L0[8], L1[8];
    #pragma unroll
    for (int r = 0; r < 8; r++) upk2(L2a[r], L0[r], L1[r]);

    size_t cbase = ((size_t)b * Nn + n0 + 2 * t) * 8;
    float c0[8], c1c[8];
    if (INIT) {
        float m0 = L0[0], m1 = L1[0];
        #pragma unroll
        for (int i = 1; i < 8; i++) { m0 = fmaxf(m0, L0[i]); m1 = fmaxf(m1, L1[i]); }
        float p0 = 0.f, p1 = 0.f;
        #pragma unroll
        for (int i = 0; i < 8; i++) {
            c0[i] = expf(L0[i] - m0); p0 += c0[i];
            c1c[i] = expf(L1[i] - m1); p1 += c1c[i];
        }
        float i0 = 1.0f / p0, i1 = 1.0f / p1;
        #pragma unroll
        for (int i = 0; i < 8; i++) { c0[i] *= i0; c1c[i] *= i1; }
    } else {
        const float4* cg = (const float4*)(g_coef + cbase);
        float4 a = cg[0], cA = cg[1], d = cg[2], e = cg[3];
        c0[0]=a.x; c0[1]=a.y; c0[2]=a.z; c0[3]=a.w;
        c0[4]=cA.x; c0[5]=cA.y; c0[6]=cA.z; c0[7]=cA.w;
        c1c[0]=d.x; c1c[1]=d.y; c1c[2]=d.z; c1c[3]=d.w;
        c1c[4]=e.x; c1c[5]=e.y; c1c[6]=e.z; c1c[7]=e.w;
    }

    ull cpk[8];
    #pragma unroll
    for (int s = 0; s < 8; s++) cpk[s] = pk2(c0[s], c1c[s]);
    float o0[8], o1[8];
    #pragma unroll
    for (int r = 0; r < 8; r++) {
        ull den2 = 0ull;
        #pragma unroll
        for (int s = 0; s < 8; s++) den2 = fma2_(cpk[s], gs2[s * 8 + r], den2);
        float dn0, dn1; upk2(den2, dn0, dn1);
        o0[r] = c0[r] * L0[r] / (dn0 + EPSV);
        o1[r] = c1c[r] * L1[r] / (dn1 + EPSV);
    }
    float4* cgw = (float4*)(g_coef + cbase);
    cgw[0] = make_float4(o0[0], o0[1], o0[2], o0[3]);
    cgw[1] = make_float4(o0[4], o0[5], o0[6], o0[7]);
    cgw[2] = make_float4(o1[0], o1[1], o1[2], o1[3]);
    cgw[3] = make_float4(o1[4], o1[5], o1[6], o1[7]);
}

// ---------------- k_xc: x@coef + ctc partials over 256-n slab (high occupancy) ----------------
__global__ __launch_bounds__(256) void k_xc(const float* __restrict__ x) {
    __shared__ __align__(16) float ct[Rr * CTS2];   // 8.3 KB
    int t = threadIdx.x, blk = blockIdx.x, b = blockIdx.y;
    int n0 = blk * NSLAB;

    {
        int nn = t;
        const float4* cg = (const float4*)(g_coef + ((size_t)b * Nn + n0 + nn) * 8);
        float4 a = cg[0], c = cg[1];
        ct[0*CTS2+nn]=a.x; ct[1*CTS2+nn]=a.y; ct[2*CTS2+nn]=a.z; ct[3*CTS2+nn]=a.w;
        ct[4*CTS2+nn]=c.x; ct[5*CTS2+nn]=c.y; ct[6*CTS2+nn]=c.z; ct[7*CTS2+nn]=c.w;
    }
    __syncthreads();

    int p  = t & 3;                  // r-pair: r = 2p, 2p+1
    int dq = t >> 2;                 // 0..63
    bool has2 = (dq < 32);           // warp-uniform
    const float* xb  = x + (size_t)b * DN + n0;
    const float* xr0 = xb + (size_t)dq * Nn;
    const float* xr1 = xb + (size_t)(dq + 64) * Nn;
    const float* xr2 = xb + (size_t)(has2 ? dq + 128 : dq) * Nn;
    const ull* c0p = (const ull*)(ct + (2 * p)     * CTS2);
    const ull* c1p = (const ull*)(ct + (2 * p + 1) * CTS2);

    ull aA0=0,aB0=0,aA1=0,aB1=0,aA2=0,aB2=0;
    #pragma unroll 4
    for (int n4 = 0; n4 < NSLAB / 4; n4++) {
        ulonglong2 c0  = *(const ulonglong2*)(c0p + n4 * 2);
        ulonglong2 c1v = *(const ulonglong2*)(c1p + n4 * 2);
        ulonglong2 x0  = *(const ulonglong2*)(xr0 + n4 * 4);
        ulonglong2 x1  = *(const ulonglong2*)(xr1 + n4 * 4);
        aA0 = fma2_(x0.x, c0.x,  aA0); aA0 = fma2_(x0.y, c0.y,  aA0);
        aB0 = fma2_(x0.x, c1v.x, aB0); aB0 = fma2_(x0.y, c1v.y, aB0);
        aA1 = fma2_(x1.x, c0.x,  aA1); aA1 = fma2_(x1.y, c0.y,  aA1);
        aB1 = fma2_(x1.x, c1v.x, aB1); aB1 = fma2_(x1.y, c1v.y, aB1);
        if (has2) {
            ulonglong2 x2 = *(const ulonglong2*)(xr2 + n4 * 4);
            aA2 = fma2_(x2.x, c0.x,  aA2); aA2 = fma2_(x2.y, c0.y,  aA2);
            aB2 = fma2_(x2.x, c1v.x, aB2); aB2 = fma2_(x2.y, c1v.y, aB2);
        }
    }
    float* outp = g_sxc + (size_t)(b * NXBLK + blk) * DR;
    {
        float la, ha, lb, hb;
        upk2(aA0, la, ha); upk2(aB0, lb, hb);
        *(float2*)(outp + dq * 8 + 2 * p) = make_float2(la + ha, lb + hb);
        upk2(aA1, la, ha); upk2(aB1, lb, hb);
        *(float2*)(outp + (dq + 64) * 8 + 2 * p) = make_float2(la + ha, lb + hb);
        if (has2) {
            upk2(aA2, la, ha); upk2(aB2, lb, hb);
            *(float2*)(outp + (dq + 128) * 8 + 2 * p) = make_float2(la + ha, lb + hb);
        }
    }

    if (t < 64) {
        int r = t >> 3, s = t & 7;
        const ull* rp = (const ull*)(ct + r * CTS2);
        const ull* sp = (const ull*)(ct + s * CTS2);
        ull a2 = 0ull, b2 = 0ull;
        #pragma unroll 4
        for (int i = 0; i < NSLAB / 4; i++) {
            a2 = fma2_(rp[2 * i],     sp[2 * i],     a2);
            b2 = fma2_(rp[2 * i + 1], sp[2 * i + 1], b2);
        }
        float lo, hi, lo2, hi2;
        upk2(a2, lo, hi); upk2(b2, lo2, hi2);
        g_sctc[(size_t)(b * NXBLK + blk) * 64 + t] = (lo + hi) + (lo2 + hi2);
    }
}

// ---------------- glue A: grid(6,B). bx<5: reduce x@coef; bx==5: ctc + t1 ----------------
__global__ void k_glueA() {
    __shared__ float sc[64];
    __shared__ float spart[256];
    int bx = blockIdx.x, b = blockIdx.y, t = threadIdx.x;
    if (bx < 5) {
        int o = bx * 256 + t;
        const float* p = g_sxc + (size_t)b * NXBLK * DR + o;
        float a0 = 0, a1 = 0, a2 = 0, a3 = 0;
        #pragma unroll 2
        for (int blk = 0; blk < NXBLK; blk += 4) {
            a0 += p[(size_t)(blk + 0) * DR];
            a1 += p[(size_t)(blk + 1) * DR];
            a2 += p[(size_t)(blk + 2) * DR];
            a3 += p[(size_t)(blk + 3) * DR];
        }
        g_xcoef[b * DR + o] = (a0 + a1) + (a2 + a3);
        return;
    }
    {
        int o = t & 63, q = t >> 6;
        const float* p = g_sctc + (size_t)b * NXBLK * 64 + o;
        float acc = 0.f;
        #pragma unroll
        for (int blk = q * 32; blk < q * 32 + 32; blk++) acc += p[blk * 64];
        spart[t] = acc;
    }
    __syncthreads();
    if (t < 64) sc[t] = (spart[t] + spart[t + 64]) + (spart[t + 128] + spart[t + 192]);
    __syncthreads();
    const float* bs = g_bases + b * KPR;
    float* t1 = g_t1 + b * KPR;
    for (int idx = t; idx < KR; idx += 256) {
        int k = idx >> 3, r = idx & 7;
        float a = 0.f;
        #pragma unroll
        for (int s = 0; s < 8; s++) a = fmaf(bs[k * 8 + s], sc[s * 8 + r], a);
        t1[idx] = a;
    }
}

// ---------------- glue B: bases *= (E^T xcoef) / (EtE @ t1 + eps) ----------------
__global__ __launch_bounds__(256) void k_glueB() {
    __shared__ float sx[DR];
    __shared__ __align__(16) float st1[KP * Rr];
    int b = blockIdx.y, t = threadIdx.x;
    for (int i = t; i < DR; i += 256) sx[i] = g_xcoef[b * DR + i];
    for (int i = t; i < KP * Rr; i += 256) st1[i] = g_t1[b * KPR + i];
    __syncthreads();
    int idx = blockIdx.x * 256 + t;
    if (idx >= KR) return;
    int k = idx >> 3, r = idx & 7;
    const float4* et = (const float4*)(g_Et + k * Dd);
    float n0 = 0.f, n1 = 0.f, n2 = 0.f, n3 = 0.f;
    #pragma unroll 8
    for (int i = 0; i < Dd / 4; i++) {
        float4 e = et[i];
        n0 = fmaf(e.x, sx[(4 * i + 0) * 8 + r], n0);
        n1 = fmaf(e.y, sx[(4 * i + 1) * 8 + r], n1);
        n2 = fmaf(e.z, sx[(4 * i + 2) * 8 + r], n2);
        n3 = fmaf(e.w, sx[(4 * i + 3) * 8 + r], n3);
    }
    float num = (n0 + n1) + (n2 + n3);
    const float4* ee = (const float4*)(g_EtE + (size_t)k * KP);
    float d0 = 0.f, d1 = 0.f, d2 = 0.f, d3 = 0.f;
    #pragma unroll 8
    for (int i = 0; i < KP / 4; i++) {
        float4 v = ee[i];
        d0 = fmaf(v.x, st1[(4 * i + 0) * 8 + r], d0);
        d1 = fmaf(v.y, st1[(4 * i + 1) * 8 + r], d1);
        d2 = fmaf(v.z, st1[(4 * i + 2) * 8 + r], d2);
        d3 = fmaf(v.w, st1[(4 * i + 3) * 8 + r], d3);
    }
    float den = (d0 + d1) + (d2 + d3);
    g_bases[b * KPR + idx] *= num / (den + EPSV);
}

// ---------------- final coef update + reconstruction, 2 columns/thread ----------------
__global__ __launch_bounds__(256) void k_final(const float* __restrict__ x,
                                               float* __restrict__ out) {
    __shared__ __align__(16) ull ebs2[Dd * Rr];
    __shared__ ull gs2[64];
    int t = threadIdx.x, blk = blockIdx.x, b = blockIdx.y;
    int n0 = blk * 512;
    for (int i = t; i < DR; i += 256) {
        float v = g_ebp[b * DR + i] + g_ebp[(Bb + b) * DR + i];
        ebs2[i] = pk2(v, v);
    }
    __syncthreads();
    if (t < 64) {
        int r = t >> 3, s = t & 7;
        const float* ef = (const float*)ebs2;
        float a = 0.f;
        #pragma unroll 8
        for (int d = 0; d < Dd; d++)
            a = fmaf(ef[(d * 8 + r) * 2], ef[(d * 8 + s) * 2], a);
        gs2[t] = pk2(a, a);
    }

    const float* xb = x + (size_t)b * DN + n0 + 2 * t;
    ull L2a[8] = {0,0,0,0,0,0,0,0};
    #pragma unroll 1
    for (int d0 = 0; d0 < Dd; d0 += 16) {
        float2 xv[16];
        #pragma unroll
        for (int i = 0; i < 16; i++) xv[i] = *(const float2*)(xb + (size_t)(d0 + i) * Nn);
        #pragma unroll
        for (int i = 0; i < 16; i++) {
            ull x2 = pk2(xv[i].x, xv[i].y);
            const ulonglong2* ep = (const ulonglong2*)(ebs2 + (d0 + i) * 8);
            ulonglong2 e0 = ep[0], e1 = ep[1], e2 = ep[2], e3 = ep[3];
            L2a[0] = fma2_(x2, e0.x, L2a[0]);
            L2a[1] = fma2_(x2, e0.y, L2a[1]);
            L2a[2] = fma2_(x2, e1.x, L2a[2]);
            L2a[3] = fma2_(x2, e1.y, L2a[3]);
            L2a[4] = fma2_(x2, e2.x, L2a[4]);
            L2a[5] = fma2_(x2, e2.y, L2a[5]);
            L2a[6] = fma2_(x2, e3.x, L2a[6]);
            L2a[7] = fma2_(x2, e3.y, L2a[7]);
        }
    }
    __syncthreads();

    float L0[8], L1[8];
    #pragma unroll
    for (int r = 0; r < 8; r++) upk2(L2a[r], L0[r], L1[r]);

    size_t cbase = ((size_t)b * Nn + n0 + 2 * t) * 8;
    const float4* cg = (const float4*)(g_coef + cbase);
    float4 a = cg[0], cA = cg[1], dV = cg[2], eV = cg[3];
    float c0[8] = {a.x, a.y, a.z, a.w, cA.x, cA.y, cA.z, cA.w};
    float c1c[8] = {dV.x, dV.y, dV.z, dV.w, eV.x, eV.y, eV.z, eV.w};

    ull cpk[8];
    #pragma unroll
    for (int s = 0; s < 8; s++) cpk[s] = pk2(c0[s], c1c[s]);
    ull c1pk[8];
    #pragma unroll
    for (int r = 0; r < 8; r++) {
        ull den2 = 0ull;
        #pragma unroll
        for (int s = 0; s < 8; s++) den2 = fma2_(cpk[s], gs2[s * 8 + r], den2);
        float dn0, dn1; upk2(den2, dn0, dn1);
        float v0 = c0[r] * L0[r] / (dn0 + EPSV);
        float v1 = c1c[r] * L1[r] / (dn1 + EPSV);
        c1pk[r] = pk2(v0, v1);
    }

    float* ob = out + (size_t)b * DN + n0 + 2 * t;
    #pragma unroll 4
    for (int d = 0; d < Dd; d++) {
        const ulonglong2* ep = (const ulonglong2*)(ebs2 + d * 8);
        ulonglong2 e0 = ep[0], e1 = ep[1], e2 = ep[2], e3 = ep[3];
        ull acc = 0ull;
        acc = fma2_(e0.x, c1pk[0], acc);
        acc = fma2_(e0.y, c1pk[1], acc);
        acc = fma2_(e1.x, c1pk[2], acc);
        acc = fma2_(e1.y, c1pk[3], acc);
        acc = fma2_(e2.x, c1pk[4], acc);
        acc = fma2_(e2.y, c1pk[5], acc);
        acc = fma2_(e3.x, c1pk[6], acc);
        acc = fma2_(e3.y, c1pk[7], acc);
        float lo, hi; upk2(acc, lo, hi);
        *(float2*)(ob + (size_t)d * Nn) = make_float2(lo, hi);
    }
}

// ---------------- launch ----------------
extern "C" void kernel_launch(void* const* d_in, const int* in_sizes, int n_in,
                              void* d_out, int out_size) {
    const float* x = (const float*)d_in[0];
    const float* binit = (const float*)d_in[1];
    float* out = (float*)d_out;

    k_init<<<Dd + Bb, 256>>>(binit);                 // 0
    k_EbG2<<<dim3(40, 2, Bb), 256>>>();              // 1
    k_EtE<<<148, 256>>>();                           // 2
    k_num<1><<<dim3(Nn / 512, Bb), 256>>>(x);        // 3  <- profiled
    k_xc<<<dim3(NXBLK, Bb), 256>>>(x);               // 4
    k_glueA<<<dim3(6, Bb), 256>>>();
    k_glueB<<<dim3(19, Bb), 256>>>();
    k_EbG2<<<dim3(40, 2, Bb), 256>>>();

    for (int s = 1; s < 4; s++) {
        k_num<0><<<dim3(Nn / 512, Bb), 256>>>(x);
        k_xc<<<dim3(NXBLK, Bb), 256>>>(x);
        k_glueA<<<dim3(6, Bb), 256>>>();
        k_glueB<<<dim3(19, Bb), 256>>>();
        k_EbG2<<<dim3(40, 2, Bb), 256>>>();
    }
    k_final<<<dim3(Nn / 512, Bb), 256>>>(x, out);
}

// round 15
// speedup vs baseline: 1.1153x; 1.0391x over previous
#include <cuda_runtime.h>
#include <math.h>

#define Bb   8
#define Dd   160
#define Nn   32768
#define Kk   589
#define KP   592                 // padded K (float4-aligned, pads are zero)
#define KPR  (KP * 8)            // padded bases/t1 batch stride
#define Rr   8
#define EPSV 1e-6f
#define DN   ((size_t)Dd * (size_t)Nn)
#define KR   (Kk * Rr)           // 4712
#define DR   (Dd * Rr)           // 1280
#define NSLAB 512                // fused-step n-slab (= block width)
#define NXBLK 64                 // Nn / NSLAB
#define CTS2  516                // ct row stride (floats), %4==0 for 16B alignment

typedef unsigned long long ull;

// ---------------- static device scratch ----------------
__device__ float g_E    [Dd * KP];
__device__ float g_Et   [Kk * Dd];
__device__ float g_EtE  [(size_t)Kk * KP];
__device__ float g_bases[Bb * KPR];
__device__ float g_t1   [Bb * KPR];
__device__ float g_ebp  [2 * Bb * DR];              // Eb split-K partials
__device__ float g_coef [(size_t)Bb * Nn * Rr];
__device__ float g_sxc  [(size_t)Bb * NXBLK * DR];
__device__ float g_sctc [Bb * NXBLK * 64];
__device__ float g_xcoef[Bb * DR];

// ---------------- packed f32x2 helpers ----------------
__device__ __forceinline__ ull pk2(float lo, float hi) {
    ull r;
    asm("mov.b64 %0, {%1, %2};" : "=l"(r) : "f"(lo), "f"(hi));
    return r;
}
__device__ __forceinline__ void upk2(ull v, float& lo, float& hi) {
    asm("mov.b64 {%0, %1}, %2;" : "=f"(lo), "=f"(hi) : "l"(v));
}
__device__ __forceinline__ ull fma2_(ull a, ull b, ull c) {
    ull d;
    asm("fma.rn.f32x2 %0, %1, %2, %3;" : "=l"(d) : "l"(a), "l"(b), "l"(c));
    return d;
}

// ---------------- init: build E (+T) and L2-normalize bases ----------------
__global__ void k_init(const float* __restrict__ bin) {
    if (blockIdx.x < Dd) {
        int d = blockIdx.x;
        for (int k = threadIdx.x; k < KP; k += blockDim.x) {
            float v = 0.f;
            if (k < Kk) {
                if (k == 588) {
                    v = 1.0f;
                } else {
                    float sig; int n;
                    if      (k < 160) { sig = 6.0f;  n = k; }
                    else if (k < 320) { sig = 8.0f;  n = k - 160; }
                    else if (k < 400) { sig = 12.0f; n = (k - 320) * 2; }
                    else if (k < 480) { sig = 15.0f; n = (k - 400) * 2; }
                    else if (k < 534) { sig = 18.0f; n = (k - 480) * 3; }
                    else              { sig = 24.0f; n = (k - 534) * 3; }
                    float diff = (float)d - (float)n;
                    v = expf(-0.5f * (diff * diff) / (2.0f * sig * sig));
                }
            }
            g_E[d * KP + k] = v;
            if (k < Kk) g_Et[k * Dd + d] = v;
        }
    } else {
        int b = blockIdx.x - Dd;
        int r = threadIdx.x >> 5;
        int l = threadIdx.x & 31;
        float ss = 0.f;
        for (int k = l; k < Kk; k += 32) {
            float v = bin[(b * Kk + k) * Rr + r];
            ss += v * v;
        }
        #pragma unroll
        for (int o = 16; o; o >>= 1) ss += __shfl_xor_sync(0xffffffffu, ss, o);
        float nrm = fmaxf(sqrtf(ss), 1e-12f);
        for (int k = l; k < Kk; k += 32)
            g_bases[b * KPR + k * Rr + r] = bin[(b * Kk + k) * Rr + r] / nrm;
        if (threadIdx.x < KPR - KR)
            g_bases[b * KPR + KR + threadIdx.x] = 0.f;
    }
}

// ---------------- EtE = E^T E : grid(148), 4 rows/block ----------------
__global__ __launch_bounds__(256) void k_EtE() {
    __shared__ float se[Dd * 4];
    int i0 = blockIdx.x * 4;
    int t = threadIdx.x;
    for (int idx = t; idx < Dd * 4; idx += 256) {
        int d = idx >> 2, i = idx & 3;
        int ki = i0 + i;
        se[idx] = (ki < Kk) ? g_Et[ki * Dd + d] : 0.f;
    }
    __syncthreads();
    int j0 = t, j1 = t + 256, j2 = t + 512;
    bool has2 = (j2 < KP);
    float a0[4] = {0,0,0,0}, a1[4] = {0,0,0,0}, a2[4] = {0,0,0,0};
    #pragma unroll 4
    for (int d = 0; d < Dd; d++) {
        float e0 = g_E[d * KP + j0];
        float e1 = g_E[d * KP + j1];
        float e2 = has2 ? g_E[d * KP + j2] : 0.f;
        #pragma unroll
        for (int i = 0; i < 4; i++) {
            float s = se[d * 4 + i];
            a0[i] = fmaf(e0, s, a0[i]);
            a1[i] = fmaf(e1, s, a1[i]);
            a2[i] = fmaf(e2, s, a2[i]);
        }
    }
    #pragma unroll
    for (int i = 0; i < 4; i++) {
        int row = i0 + i;
        if (row < Kk) {
            g_EtE[(size_t)row * KP + j0] = a0[i];
            g_EtE[(size_t)row * KP + j1] = a1[i];
            if (has2) g_EtE[(size_t)row * KP + j2] = a2[i];
        }
    }
}

// ---------------- Eb partials: grid(40, 2, Bb), 8 lanes per output ----------------
__global__ __launch_bounds__(256) void k_EbG2() {
    int t = threadIdx.x;
    int q = blockIdx.y, b = blockIdx.z;
    int out = t >> 3, kg = t & 7;
    int idx = blockIdx.x * 32 + out;               // 0..1279
    int d = idx >> 3, r = idx & 7;
    const float* Erow = g_E + d * KP + q * 296 + kg;
    const float* brow = g_bases + b * KPR + (q * 296 + kg) * 8 + r;
    float acc0 = 0.f, acc1 = 0.f;
    #pragma unroll
    for (int i = 0; i < 36; i += 2) {
        acc0 = fmaf(Erow[8 * i],       brow[64 * i],       acc0);
        acc1 = fmaf(Erow[8 * (i + 1)], brow[64 * (i + 1)], acc1);
    }
    acc0 = fmaf(Erow[8 * 36], brow[64 * 36], acc0);
    float acc = acc0 + acc1;
    acc += __shfl_down_sync(0xffffffffu, acc, 4);
    acc += __shfl_down_sync(0xffffffffu, acc, 2);
    acc += __shfl_down_sync(0xffffffffu, acc, 1);
    if (kg == 0) g_ebp[(q * Bb + b) * DR + idx] = acc;
}

// ---------------- fused step: coef update (2 cols/thread) + x@coef + ctc ----------------
template<int INIT>
__global__ __launch_bounds__(256) void k_step(const float* __restrict__ x) {
    __shared__ __align__(16) ull ebs2[Dd * Rr];    // (e,e) pairs, 10.2 KB
    __shared__ ull gs2[64];
    __shared__ __align__(16) float ct[Rr * CTS2];  // coef transposed, 16.5 KB
    int t = threadIdx.x, blk = blockIdx.x, b = blockIdx.y;
    int n0 = blk * NSLAB;

    for (int i = t; i < DR; i += 256) {
        float v = g_ebp[b * DR + i] + g_ebp[(Bb + b) * DR + i];
        ebs2[i] = pk2(v, v);
    }
    __syncthreads();
    if (t < 64) {
        int r = t >> 3, s = t & 7;
        const float* ef = (const float*)ebs2;
        float a = 0.f;
        #pragma unroll 8
        for (int d = 0; d < Dd; d++)
            a = fmaf(ef[(d * 8 + r) * 2], ef[(d * 8 + s) * 2], a);
        gs2[t] = pk2(a, a);
    }

    // ---- phase 1: L = x^T Eb for 2 columns ----
    const float* xb = x + (size_t)b * DN + n0 + 2 * t;
    ull L2a[8] = {0,0,0,0,0,0,0,0};
    #pragma unroll 1
    for (int d0 = 0; d0 < Dd; d0 += 16) {
        float2 xv[16];
        #pragma unroll
        for (int i = 0; i < 16; i++) xv[i] = *(const float2*)(xb + (size_t)(d0 + i) * Nn);
        #pragma unroll
        for (int i = 0; i < 16; i++) {
            ull x2 = pk2(xv[i].x, xv[i].y);
            const ulonglong2* ep = (const ulonglong2*)(ebs2 + (d0 + i) * 8);
            ulonglong2 e0 = ep[0], e1 = ep[1], e2 = ep[2], e3 = ep[3];
            L2a[0] = fma2_(x2, e0.x, L2a[0]);
            L2a[1] = fma2_(x2, e0.y, L2a[1]);
            L2a[2] = fma2_(x2, e1.x, L2a[2]);
            L2a[3] = fma2_(x2, e1.y, L2a[3]);
            L2a[4] = fma2_(x2, e2.x, L2a[4]);
            L2a[5] = fma2_(x2, e2.y, L2a[5]);
            L2a[6] = fma2_(x2, e3.x, L2a[6]);
            L2a[7] = fma2_(x2, e3.y, L2a[7]);
        }
    }
    __syncthreads();   // gs2 visible

    float L0[8], L1[8];
    #pragma unroll
    for (int r = 0; r < 8; r++) upk2(L2a[r], L0[r], L1[r]);

    size_t cbase = ((size_t)b * Nn + n0 + 2 * t) * 8;
    float c0[8], c1c[8];
    if (INIT) {
        float m0 = L0[0], m1 = L1[0];
        #pragma unroll
        for (int i = 1; i < 8; i++) { m0 = fmaxf(m0, L0[i]); m1 = fmaxf(m1, L1[i]); }
        float p0 = 0.f, p1 = 0.f;
        #pragma unroll
        for (int i = 0; i < 8; i++) {
            c0[i] = expf(L0[i] - m0); p0 += c0[i];
            c1c[i] = expf(L1[i] - m1); p1 += c1c[i];
        }
        float i0 = 1.0f / p0, i1 = 1.0f / p1;
        #pragma unroll
        for (int i = 0; i < 8; i++) { c0[i] *= i0; c1c[i] *= i1; }
    } else {
        const float4* cg = (const float4*)(g_coef + cbase);
        float4 a = cg[0], cA = cg[1], d = cg[2], e = cg[3];
        c0[0]=a.x; c0[1]=a.y; c0[2]=a.z; c0[3]=a.w;
        c0[4]=cA.x; c0[5]=cA.y; c0[6]=cA.z; c0[7]=cA.w;
        c1c[0]=d.x; c1c[1]=d.y; c1c[2]=d.z; c1c[3]=d.w;
        c1c[4]=e.x; c1c[5]=e.y; c1c[6]=e.z; c1c[7]=e.w;
    }

    ull cpk[8];
    #pragma unroll
    for (int s = 0; s < 8; s++) cpk[s] = pk2(c0[s], c1c[s]);
    float o0[8], o1[8];
    #pragma unroll
    for (int r = 0; r < 8; r++) {
        ull den2 = 0ull;
        #pragma unroll
        for (int s = 0; s < 8; s++) den2 = fma2_(cpk[s], gs2[s * 8 + r], den2);
        float dn0, dn1; upk2(den2, dn0, dn1);
        o0[r] = c0[r] * L0[r] / (dn0 + EPSV);
        o1[r] = c1c[r] * L1[r] / (dn1 + EPSV);
    }
    float4* cgw = (float4*)(g_coef + cbase);
    cgw[0] = make_float4(o0[0], o0[1], o0[2], o0[3]);
    cgw[1] = make_float4(o0[4], o0[5], o0[6], o0[7]);
    cgw[2] = make_float4(o1[0], o1[1], o1[2], o1[3]);
    cgw[3] = make_float4(o1[4], o1[5], o1[6], o1[7]);
    #pragma unroll
    for (int r = 0; r < 8; r++)
        *(float2*)(ct + r * CTS2 + 2 * t) = make_float2(o0[r], o1[r]);
    __syncthreads();

    // ---- phase 2: xcoef partials + ctc (x re-read from global, L2-warm) ----
    {
        int p  = t & 3;                  // r-pair: r = 2p, 2p+1
        int dq = t >> 2;                 // 0..63
        bool has2 = (dq < 32);           // warp-uniform
        const float* xs  = x + (size_t)b * DN + n0;
        const float* xr0 = xs + (size_t)dq * Nn;
        const float* xr1 = xs + (size_t)(dq + 64) * Nn;
        const float* xr2 = xs + (size_t)(has2 ? dq + 128 : dq) * Nn;
        const ull* c0p = (const ull*)(ct + (2 * p)     * CTS2);
        const ull* c1p = (const ull*)(ct + (2 * p + 1) * CTS2);

        ull aA0=0,aB0=0,aA1=0,aB1=0,aA2=0,aB2=0;
        #pragma unroll 4
        for (int n4 = 0; n4 < NSLAB / 4; n4++) {
            ulonglong2 cc0 = *(const ulonglong2*)(c0p + n4 * 2);
            ulonglong2 cc1 = *(const ulonglong2*)(c1p + n4 * 2);
            ulonglong2 x0  = *(const ulonglong2*)(xr0 + n4 * 4);
            ulonglong2 x1  = *(const ulonglong2*)(xr1 + n4 * 4);
            aA0 = fma2_(x0.x, cc0.x, aA0); aA0 = fma2_(x0.y, cc0.y, aA0);
            aB0 = fma2_(x0.x, cc1.x, aB0); aB0 = fma2_(x0.y, cc1.y, aB0);
            aA1 = fma2_(x1.x, cc0.x, aA1); aA1 = fma2_(x1.y, cc0.y, aA1);
            aB1 = fma2_(x1.x, cc1.x, aB1); aB1 = fma2_(x1.y, cc1.y, aB1);
            if (has2) {
                ulonglong2 x2 = *(const ulonglong2*)(xr2 + n4 * 4);
                aA2 = fma2_(x2.x, cc0.x, aA2); aA2 = fma2_(x2.y, cc0.y, aA2);
                aB2 = fma2_(x2.x, cc1.x, aB2); aB2 = fma2_(x2.y, cc1.y, aB2);
            }
        }
        float* outp = g_sxc + (size_t)(b * NXBLK + blk) * DR;
        float la, ha, lb, hb;
        upk2(aA0, la, ha); upk2(aB0, lb, hb);
        *(float2*)(outp + dq * 8 + 2 * p) = make_float2(la + ha, lb + hb);
        upk2(aA1, la, ha); upk2(aB1, lb, hb);
        *(float2*)(outp + (dq + 64) * 8 + 2 * p) = make_float2(la + ha, lb + hb);
        if (has2) {
            upk2(aA2, la, ha); upk2(aB2, lb, hb);
            *(float2*)(outp + (dq + 128) * 8 + 2 * p) = make_float2(la + ha, lb + hb);
        }
    }

    if (t < 64) {
        int r = t >> 3, s = t & 7;
        const ull* rp = (const ull*)(ct + r * CTS2);
        const ull* sp = (const ull*)(ct + s * CTS2);
        ull a2 = 0ull, b2 = 0ull;
        #pragma unroll 4
        for (int i = 0; i < NSLAB / 4; i++) {
            a2 = fma2_(rp[2 * i],     sp[2 * i],     a2);
            b2 = fma2_(rp[2 * i + 1], sp[2 * i + 1], b2);
        }
        float lo, hi, lo2, hi2;
        upk2(a2, lo, hi); upk2(b2, lo2, hi2);
        g_sctc[(size_t)(b * NXBLK + blk) * 64 + t] = (lo + hi) + (lo2 + hi2);
    }
}

// ---------------- glue A: grid(6,B). bx<5: reduce x@coef; bx==5: ctc + t1 ----------------
__global__ void k_glueA() {
    __shared__ float sc[64];
    __shared__ float spart[256];
    int bx = blockIdx.x, b = blockIdx.y, t = threadIdx.x;
    if (bx < 5) {
        int o = bx * 256 + t;
        const float* p = g_sxc + (size_t)b * NXBLK * DR + o;
        float a0 = 0, a1 = 0, a2 = 0, a3 = 0;
        #pragma unroll 2
        for (int blk = 0; blk < NXBLK; blk += 4) {
            a0 += p[(size_t)(blk + 0) * DR];
            a1 += p[(size_t)(blk + 1) * DR];
            a2 += p[(size_t)(blk + 2) * DR];
            a3 += p[(size_t)(blk + 3) * DR];
        }
        g_xcoef[b * DR + o] = (a0 + a1) + (a2 + a3);
        return;
    }
    {
        int o = t & 63, q = t >> 6;
        const float* p = g_sctc + (size_t)b * NXBLK * 64 + o;
        float acc = 0.f;
        #pragma unroll
        for (int blk = q * 16; blk < q * 16 + 16; blk++) acc += p[blk * 64];
        spart[t] = acc;
    }
    __syncthreads();
    if (t < 64) sc[t] = (spart[t] + spart[t + 64]) + (spart[t + 128] + spart[t + 192]);
    __syncthreads();
    const float* bs = g_bases + b * KPR;
    float* t1 = g_t1 + b * KPR;
    for (int idx = t; idx < KR; idx += 256) {
        int k = idx >> 3, r = idx & 7;
        float a = 0.f;
        #pragma unroll
        for (int s = 0; s < 8; s++) a = fmaf(bs[k * 8 + s], sc[s * 8 + r], a);
        t1[idx] = a;
    }
}

// ---------------- glue B: bases *= (E^T xcoef) / (EtE @ t1 + eps) ----------------
__global__ __launch_bounds__(256) void k_glueB() {
    __shared__ float sx[DR];
    __shared__ __align__(16) float st1[KP * Rr];
    int b = blockIdx.y, t = threadIdx.x;
    for (int i = t; i < DR; i += 256) sx[i] = g_xcoef[b * DR + i];
    for (int i = t; i < KP * Rr; i += 256) st1[i] = g_t1[b * KPR + i];
    __syncthreads();
    int idx = blockIdx.x * 256 + t;
    if (idx >= KR) return;
    int k = idx >> 3, r = idx & 7;
    const float4* et = (const float4*)(g_Et + k * Dd);
    float n0 = 0.f, n1 = 0.f, n2 = 0.f, n3 = 0.f;
    #pragma unroll 8
    for (int i = 0; i < Dd / 4; i++) {
        float4 e = et[i];
        n0 = fmaf(e.x, sx[(4 * i + 0) * 8 + r], n0);
        n1 = fmaf(e.y, sx[(4 * i + 1) * 8 + r], n1);
        n2 = fmaf(e.z, sx[(4 * i + 2) * 8 + r], n2);
        n3 = fmaf(e.w, sx[(4 * i + 3) * 8 + r], n3);
    }
    float num = (n0 + n1) + (n2 + n3);
    const float4* ee = (const float4*)(g_EtE + (size_t)k * KP);
    float d0 = 0.f, d1 = 0.f, d2 = 0.f, d3 = 0.f;
    #pragma unroll 8
    for (int i = 0; i < KP / 4; i++) {
        float4 v = ee[i];
        d0 = fmaf(v.x, st1[(4 * i + 0) * 8 + r], d0);
        d1 = fmaf(v.y, st1[(4 * i + 1) * 8 + r], d1);
        d2 = fmaf(v.z, st1[(4 * i + 2) * 8 + r], d2);
        d3 = fmaf(v.w, st1[(4 * i + 3) * 8 + r], d3);
    }
    float den = (d0 + d1) + (d2 + d3);
    g_bases[b * KPR + idx] *= num / (den + EPSV);
}

// ---------------- final coef update + reconstruction, 2 columns/thread ----------------
__global__ __launch_bounds__(256) void k_final(const float* __restrict__ x,
                                               float* __restrict__ out) {
    __shared__ __align__(16) ull ebs2[Dd * Rr];
    __shared__ ull gs2[64];
    int t = threadIdx.x, blk = blockIdx.x, b = blockIdx.y;
    int n0 = blk * 512;
    for (int i = t; i < DR; i += 256) {
        float v = g_ebp[b * DR + i] + g_ebp[(Bb + b) * DR + i];
        ebs2[i] = pk2(v, v);
    }
    __syncthreads();
    if (t < 64) {
        int r = t >> 3, s = t & 7;
        const float* ef = (const float*)ebs2;
        float a = 0.f;
        #pragma unroll 8
        for (int d = 0; d < Dd; d++)
            a = fmaf(ef[(d * 8 + r) * 2], ef[(d * 8 + s) * 2], a);
        gs2[t] = pk2(a, a);
    }

    const float* xb = x + (size_t)b * DN + n0 + 2 * t;
    ull L2a[8] = {0,0,0,0,0,0,0,0};
    #pragma unroll 1
    for (int d0 = 0; d0 < Dd; d0 += 16) {
        float2 xv[16];
        #pragma unroll
        for (int i = 0; i < 16; i++) xv[i] = *(const float2*)(xb + (size_t)(d0 + i) * Nn);
        #pragma unroll
        for (int i = 0; i < 16; i++) {
            ull x2 = pk2(xv[i].x, xv[i].y);
            const ulonglong2* ep = (const ulonglong2*)(ebs2 + (d0 + i) * 8);
            ulonglong2 e0 = ep[0], e1 = ep[1], e2 = ep[2], e3 = ep[3];
            L2a[0] = fma2_(x2, e0.x, L2a[0]);
            L2a[1] = fma2_(x2, e0.y, L2a[1]);
            L2a[2] = fma2_(x2, e1.x, L2a[2]);
            L2a[3] = fma2_(x2, e1.y, L2a[3]);
            L2a[4] = fma2_(x2, e2.x, L2a[4]);
            L2a[5] = fma2_(x2, e2.y, L2a[5]);
            L2a[6] = fma2_(x2, e3.x, L2a[6]);
            L2a[7] = fma2_(x2, e3.y, L2a[7]);
        }
    }
    __syncthreads();

    float L0[8], L1[8];
    #pragma unroll
    for (int r = 0; r < 8; r++) upk2(L2a[r], L0[r], L1[r]);

    size_t cbase = ((size_t)b * Nn + n0 + 2 * t) * 8;
    const float4* cg = (const float4*)(g_coef + cbase);
    float4 a = cg[0], cA = cg[1], dV = cg[2], eV = cg[3];
    float c0[8] = {a.x, a.y, a.z, a.w, cA.x, cA.y, cA.z, cA.w};
    float c1c[8] = {dV.x, dV.y, dV.z, dV.w, eV.x, eV.y, eV.z, eV.w};

    ull cpk[8];
    #pragma unroll
    for (int s = 0; s < 8; s++) cpk[s] = pk2(c0[s], c1c[s]);
    ull c1pk[8];
    #pragma unroll
    for (int r = 0; r < 8; r++) {
        ull den2 = 0ull;
        #pragma unroll
        for (int s = 0; s < 8; s++) den2 = fma2_(cpk[s], gs2[s * 8 + r], den2);
        float dn0, dn1; upk2(den2, dn0, dn1);
        float v0 = c0[r] * L0[r] / (dn0 + EPSV);
        float v1 = c1c[r] * L1[r] / (dn1 + EPSV);
        c1pk[r] = pk2(v0, v1);
    }

    float* ob = out + (size_t)b * DN + n0 + 2 * t;
    #pragma unroll 4
    for (int d = 0; d < Dd; d++) {
        const ulonglong2* ep = (const ulonglong2*)(ebs2 + d * 8);
        ulonglong2 e0 = ep[0], e1 = ep[1], e2 = ep[2], e3 = ep[3];
        ull acc = 0ull;
        acc = fma2_(e0.x, c1pk[0], acc);
        acc = fma2_(e0.y, c1pk[1], acc);
        acc = fma2_(e1.x, c1pk[2], acc);
        acc = fma2_(e1.y, c1pk[3], acc);
        acc = fma2_(e2.x, c1pk[4], acc);
        acc = fma2_(e2.y, c1pk[5], acc);
        acc = fma2_(e3.x, c1pk[6], acc);
        acc = fma2_(e3.y, c1pk[7], acc);
        float lo, hi; upk2(acc, lo, hi);
        *(float2*)(ob + (size_t)d * Nn) = make_float2(lo, hi);
    }
}

// ---------------- launch ----------------
extern "C" void kernel_launch(void* const* d_in, const int* in_sizes, int n_in,
                              void* d_out, int out_size) {
    const float* x = (const float*)d_in[0];
    const float* binit = (const float*)d_in[1];
    float* out = (float*)d_out;

    k_init<<<Dd + Bb, 256>>>(binit);                 // 0
    k_EbG2<<<dim3(40, 2, Bb), 256>>>();              // 1
    k_EtE<<<148, 256>>>();                           // 2
    k_step<1><<<dim3(Nn / NSLAB, Bb), 256>>>(x);     // 3  <- profiled
    k_glueA<<<dim3(6, Bb), 256>>>();
    k_glueB<<<dim3(19, Bb), 256>>>();
    k_EbG2<<<dim3(40, 2, Bb), 256>>>();

    for (int s = 1; s < 4; s++) {
        k_step<0><<<dim3(Nn / NSLAB, Bb), 256>>>(x);
        k_glueA<<<dim3(6, Bb), 256>>>();
        k_glueB<<<dim3(19, Bb), 256>>>();
        k_EbG2<<<dim3(40, 2, Bb), 256>>>();
    }
    k_final<<<dim3(Nn / 512, Bb), 256>>>(x, out);
}

// round 16
// speedup vs baseline: 1.1401x; 1.0223x over previous
#include <cuda_runtime.h>
#include <math.h>

#define Bb   8
#define Dd   160
#define Nn   32768
#define Kk   589
#define KP   592                 // padded K (float4-aligned, pads are zero)
#define KPR  (KP * 8)            // padded bases/t1 batch stride
#define Rr   8
#define EPSV 1e-6f
#define DN   ((size_t)Dd * (size_t)Nn)
#define KR   (Kk * Rr)           // 4712
#define DR   (Dd * Rr)           // 1280
#define NSLAB 512                // fused-step n-slab
#define NXBLK 64                 // Nn / NSLAB
#define CTS2  516                // ct row stride (floats)

typedef unsigned long long ull;

// ---------------- static device scratch ----------------
__device__ float g_E    [Dd * KP];
__device__ float g_Et   [Kk * Dd];
__device__ float g_EtE  [(size_t)Kk * KP];
__device__ float g_bases[Bb * KPR];
__device__ float g_ebp  [2 * Bb * DR];              // Eb split-K partials
__device__ float g_coef [(size_t)Bb * Nn * Rr];
__device__ float g_sxc  [(size_t)Bb * NXBLK * DR];
__device__ float g_sctc [Bb * NXBLK * 64];

// ---------------- packed f32x2 helpers ----------------
__device__ __forceinline__ ull pk2(float lo, float hi) {
    ull r;
    asm("mov.b64 %0, {%1, %2};" : "=l"(r) : "f"(lo), "f"(hi));
    return r;
}
__device__ __forceinline__ void upk2(ull v, float& lo, float& hi) {
    asm("mov.b64 {%0, %1}, %2;" : "=f"(lo), "=f"(hi) : "l"(v));
}
__device__ __forceinline__ ull fma2_(ull a, ull b, ull c) {
    ull d;
    asm("fma.rn.f32x2 %0, %1, %2, %3;" : "=l"(d) : "l"(a), "l"(b), "l"(c));
    return d;
}

// ---------------- init: build E (+T) and L2-normalize bases ----------------
__global__ void k_init(const float* __restrict__ bin) {
    if (blockIdx.x < Dd) {
        int d = blockIdx.x;
        for (int k = threadIdx.x; k < KP; k += blockDim.x) {
            float v = 0.f;
            if (k < Kk) {
                if (k == 588) {
                    v = 1.0f;
                } else {
                    float sig; int n;
                    if      (k < 160) { sig = 6.0f;  n = k; }
                    else if (k < 320) { sig = 8.0f;  n = k - 160; }
                    else if (k < 400) { sig = 12.0f; n = (k - 320) * 2; }
                    else if (k < 480) { sig = 15.0f; n = (k - 400) * 2; }
                    else if (k < 534) { sig = 18.0f; n = (k - 480) * 3; }
                    else              { sig = 24.0f; n = (k - 534) * 3; }
                    float diff = (float)d - (float)n;
                    v = expf(-0.5f * (diff * diff) / (2.0f * sig * sig));
                }
            }
            g_E[d * KP + k] = v;
            if (k < Kk) g_Et[k * Dd + d] = v;
        }
    } else {
        int b = blockIdx.x - Dd;
        int r = threadIdx.x >> 5;
        int l = threadIdx.x & 31;
        float ss = 0.f;
        for (int k = l; k < Kk; k += 32) {
            float v = bin[(b * Kk + k) * Rr + r];
            ss += v * v;
        }
        #pragma unroll
        for (int o = 16; o; o >>= 1) ss += __shfl_xor_sync(0xffffffffu, ss, o);
        float nrm = fmaxf(sqrtf(ss), 1e-12f);
        for (int k = l; k < Kk; k += 32)
            g_bases[b * KPR + k * Rr + r] = bin[(b * Kk + k) * Rr + r] / nrm;
        if (threadIdx.x < KPR - KR)
            g_bases[b * KPR + KR + threadIdx.x] = 0.f;
    }
}

// ---------------- EtE = E^T E : grid(148), 4 rows/block ----------------
__global__ __launch_bounds__(256) void k_EtE() {
    __shared__ float se[Dd * 4];
    int i0 = blockIdx.x * 4;
    int t = threadIdx.x;
    for (int idx = t; idx < Dd * 4; idx += 256) {
        int d = idx >> 2, i = idx & 3;
        int ki = i0 + i;
        se[idx] = (ki < Kk) ? g_Et[ki * Dd + d] : 0.f;
    }
    __syncthreads();
    int j0 = t, j1 = t + 256, j2 = t + 512;
    bool has2 = (j2 < KP);
    float a0[4] = {0,0,0,0}, a1[4] = {0,0,0,0}, a2[4] = {0,0,0,0};
    #pragma unroll 4
    for (int d = 0; d < Dd; d++) {
        float e0 = g_E[d * KP + j0];
        float e1 = g_E[d * KP + j1];
        float e2 = has2 ? g_E[d * KP + j2] : 0.f;
        #pragma unroll
        for (int i = 0; i < 4; i++) {
            float s = se[d * 4 + i];
            a0[i] = fmaf(e0, s, a0[i]);
            a1[i] = fmaf(e1, s, a1[i]);
            a2[i] = fmaf(e2, s, a2[i]);
        }
    }
    #pragma unroll
    for (int i = 0; i < 4; i++) {
        int row = i0 + i;
        if (row < Kk) {
            g_EtE[(size_t)row * KP + j0] = a0[i];
            g_EtE[(size_t)row * KP + j1] = a1[i];
            if (has2) g_EtE[(size_t)row * KP + j2] = a2[i];
        }
    }
}

// ---------------- Eb partials: grid(40, 2, Bb), 8 lanes per output ----------------
__global__ __launch_bounds__(256) void k_EbG2() {
    int t = threadIdx.x;
    int q = blockIdx.y, b = blockIdx.z;
    int out = t >> 3, kg = t & 7;
    int idx = blockIdx.x * 32 + out;               // 0..1279
    int d = idx >> 3, r = idx & 7;
    const float* Erow = g_E + d * KP + q * 296 + kg;
    const float* brow = g_bases + b * KPR + (q * 296 + kg) * 8 + r;
    float acc0 = 0.f, acc1 = 0.f;
    #pragma unroll
    for (int i = 0; i < 36; i += 2) {
        acc0 = fmaf(Erow[8 * i],       brow[64 * i],       acc0);
        acc1 = fmaf(Erow[8 * (i + 1)], brow[64 * (i + 1)], acc1);
    }
    acc0 = fmaf(Erow[8 * 36], brow[64 * 36], acc0);
    float acc = acc0 + acc1;
    acc += __shfl_down_sync(0xffffffffu, acc, 4);
    acc += __shfl_down_sync(0xffffffffu, acc, 2);
    acc += __shfl_down_sync(0xffffffffu, acc, 1);
    if (kg == 0) g_ebp[(q * Bb + b) * DR + idx] = acc;
}

// ---------------- fused step: coef update (2 cols/thread) + x@coef + ctc ----------------
template<int INIT>
__global__ __launch_bounds__(256) void k_step(const float* __restrict__ x) {
    __shared__ __align__(16) ull ebs2[Dd * Rr];    // (e,e) pairs
    __shared__ ull gs2[64];
    __shared__ __align__(16) float ct[Rr * CTS2];  // coef transposed
    int t = threadIdx.x, blk = blockIdx.x, b = blockIdx.y;
    int n0 = blk * NSLAB;

    for (int i = t; i < DR; i += 256) {
        float v = g_ebp[b * DR + i] + g_ebp[(Bb + b) * DR + i];
        ebs2[i] = pk2(v, v);
    }
    __syncthreads();
    if (t < 64) {
        int r = t >> 3, s = t & 7;
        const float* ef = (const float*)ebs2;
        float a = 0.f;
        #pragma unroll 8
        for (int d = 0; d < Dd; d++)
            a = fmaf(ef[(d * 8 + r) * 2], ef[(d * 8 + s) * 2], a);
        gs2[t] = pk2(a, a);
    }

    // ---- phase 1 ----
    const float* xb = x + (size_t)b * DN + n0 + 2 * t;
    ull L2a[8] = {0,0,0,0,0,0,0,0};
    #pragma unroll 1
    for (int d0 = 0; d0 < Dd; d0 += 16) {
        float2 xv[16];
        #pragma unroll
        for (int i = 0; i < 16; i++) xv[i] = *(const float2*)(xb + (size_t)(d0 + i) * Nn);
        #pragma unroll
        for (int i = 0; i < 16; i++) {
            ull x2 = pk2(xv[i].x, xv[i].y);
            const ulonglong2* ep = (const ulonglong2*)(ebs2 + (d0 + i) * 8);
            ulonglong2 e0 = ep[0], e1 = ep[1], e2 = ep[2], e3 = ep[3];
            L2a[0] = fma2_(x2, e0.x, L2a[0]);
            L2a[1] = fma2_(x2, e0.y, L2a[1]);
            L2a[2] = fma2_(x2, e1.x, L2a[2]);
            L2a[3] = fma2_(x2, e1.y, L2a[3]);
            L2a[4] = fma2_(x2, e2.x, L2a[4]);
            L2a[5] = fma2_(x2, e2.y, L2a[5]);
            L2a[6] = fma2_(x2, e3.x, L2a[6]);
            L2a[7] = fma2_(x2, e3.y, L2a[7]);
        }
    }
    __syncthreads();

    float L0[8], L1[8];
    #pragma unroll
    for (int r = 0; r < 8; r++) upk2(L2a[r], L0[r], L1[r]);

    size_t cbase = ((size_t)b * Nn + n0 + 2 * t) * 8;
    float c0[8], c1c[8];
    if (INIT) {
        float m0 = L0[0], m1 = L1[0];
        #pragma unroll
        for (int i = 1; i < 8; i++) { m0 = fmaxf(m0, L0[i]); m1 = fmaxf(m1, L1[i]); }
        float p0 = 0.f, p1 = 0.f;
        #pragma unroll
        for (int i = 0; i < 8; i++) {
            c0[i] = expf(L0[i] - m0); p0 += c0[i];
            c1c[i] = expf(L1[i] - m1); p1 += c1c[i];
        }
        float i0 = 1.0f / p0, i1 = 1.0f / p1;
        #pragma unroll
        for (int i = 0; i < 8; i++) { c0[i] *= i0; c1c[i] *= i1; }
    } else {
        const float4* cg = (const float4*)(g_coef + cbase);
        float4 a = cg[0], cA = cg[1], d = cg[2], e = cg[3];
        c0[0]=a.x; c0[1]=a.y; c0[2]=a.z; c0[3]=a.w;
        c0[4]=cA.x; c0[5]=cA.y; c0[6]=cA.z; c0[7]=cA.w;
        c1c[0]=d.x; c1c[1]=d.y; c1c[2]=d.z; c1c[3]=d.w;
        c1c[4]=e.x; c1c[5]=e.y; c1c[6]=e.z; c1c[7]=e.w;
    }

    ull cpk[8];
    #pragma unroll
    for (int s = 0; s < 8; s++) cpk[s] = pk2(c0[s], c1c[s]);
    float o0[8], o1[8];
    #pragma unroll
    for (int r = 0; r < 8; r++) {
        ull den2 = 0ull;
        #pragma unroll
        for (int s = 0; s < 8; s++) den2 = fma2_(cpk[s], gs2[s * 8 + r], den2);
        float dn0, dn1; upk2(den2, dn0, dn1);
        o0[r] = c0[r] * L0[r] / (dn0 + EPSV);
        o1[r] = c1c[r] * L1[r] / (dn1 + EPSV);
    }
    float4* cgw = (float4*)(g_coef + cbase);
    cgw[0] = make_float4(o0[0], o0[1], o0[2], o0[3]);
    cgw[1] = make_float4(o0[4], o0[5], o0[6], o0[7]);
    cgw[2] = make_float4(o1[0], o1[1], o1[2], o1[3]);
    cgw[3] = make_float4(o1[4], o1[5], o1[6], o1[7]);
    #pragma unroll
    for (int r = 0; r < 8; r++)
        *(float2*)(ct + r * CTS2 + 2 * t) = make_float2(o0[r], o1[r]);
    __syncthreads();

    // ---- phase 2 ----
    {
        int p  = t & 3;
        int dq = t >> 2;
        bool has2 = (dq < 32);
        const float* xs  = x + (size_t)b * DN + n0;
        const float* xr0 = xs + (size_t)dq * Nn;
        const float* xr1 = xs + (size_t)(dq + 64) * Nn;
        const float* xr2 = xs + (size_t)(has2 ? dq + 128 : dq) * Nn;
        const ull* c0p = (const ull*)(ct + (2 * p)     * CTS2);
        const ull* c1p = (const ull*)(ct + (2 * p + 1) * CTS2);

        ull aA0=0,aB0=0,aA1=0,aB1=0,aA2=0,aB2=0;
        #pragma unroll 4
        for (int n4 = 0; n4 < NSLAB / 4; n4++) {
            ulonglong2 cc0 = *(const ulonglong2*)(c0p + n4 * 2);
            ulonglong2 cc1 = *(const ulonglong2*)(c1p + n4 * 2);
            ulonglong2 x0  = *(const ulonglong2*)(xr0 + n4 * 4);
            ulonglong2 x1  = *(const ulonglong2*)(xr1 + n4 * 4);
            aA0 = fma2_(x0.x, cc0.x, aA0); aA0 = fma2_(x0.y, cc0.y, aA0);
            aB0 = fma2_(x0.x, cc1.x, aB0); aB0 = fma2_(x0.y, cc1.y, aB0);
            aA1 = fma2_(x1.x, cc0.x, aA1); aA1 = fma2_(x1.y, cc0.y, aA1);
            aB1 = fma2_(x1.x, cc1.x, aB1); aB1 = fma2_(x1.y, cc1.y, aB1);
            if (has2) {
                ulonglong2 x2 = *(const ulonglong2*)(xr2 + n4 * 4);
                aA2 = fma2_(x2.x, cc0.x, aA2); aA2 = fma2_(x2.y, cc0.y, aA2);
                aB2 = fma2_(x2.x, cc1.x, aB2); aB2 = fma2_(x2.y, cc1.y, aB2);
            }
        }
        float* outp = g_sxc + (size_t)(b * NXBLK + blk) * DR;
        float la, ha, lb, hb;
        upk2(aA0, la, ha); upk2(aB0, lb, hb);
        *(float2*)(outp + dq * 8 + 2 * p) = make_float2(la + ha, lb + hb);
        upk2(aA1, la, ha); upk2(aB1, lb, hb);
        *(float2*)(outp + (dq + 64) * 8 + 2 * p) = make_float2(la + ha, lb + hb);
        if (has2) {
            upk2(aA2, la, ha); upk2(aB2, lb, hb);
            *(float2*)(outp + (dq + 128) * 8 + 2 * p) = make_float2(la + ha, lb + hb);
        }
    }

    if (t < 64) {
        int r = t >> 3, s = t & 7;
        const ull* rp = (const ull*)(ct + r * CTS2);
        const ull* sp = (const ull*)(ct + s * CTS2);
        ull a2 = 0ull, b2 = 0ull;
        #pragma unroll 4
        for (int i = 0; i < NSLAB / 4; i++) {
            a2 = fma2_(rp[2 * i],     sp[2 * i],     a2);
            b2 = fma2_(rp[2 * i + 1], sp[2 * i + 1], b2);
        }
        float lo, hi, lo2, hi2;
        upk2(a2, lo, hi); upk2(b2, lo2, hi2);
        g_sctc[(size_t)(b * NXBLK + blk) * 64 + t] = (lo + hi) + (lo2 + hi2);
    }
}

// ---------------- merged glue: reduce partials + t1 + bases update, grid(19,B) ----------------
__global__ __launch_bounds__(256) void k_glue() {
    __shared__ float sc[64];
    __shared__ float spart[256];
    __shared__ float sx[DR];
    __shared__ __align__(16) float st1[KP * Rr];
    int b = blockIdx.y, t = threadIdx.x;

    // reduce ctc partials (NXBLK=64)
    {
        int o = t & 63, q = t >> 6;
        const float* p = g_sctc + (size_t)b * NXBLK * 64 + o;
        float acc = 0.f;
        #pragma unroll
        for (int blk = q * 16; blk < q * 16 + 16; blk++) acc += p[blk * 64];
        spart[t] = acc;
    }
    // reduce xcoef partials into smem (full DR vector, replicated per block)
    for (int o = t; o < DR; o += 256) {
        const float* p = g_sxc + (size_t)b * NXBLK * DR + o;
        float a0 = 0, a1 = 0, a2 = 0, a3 = 0;
        #pragma unroll 2
        for (int blk = 0; blk < NXBLK; blk += 4) {
            a0 += p[(size_t)(blk + 0) * DR];
            a1 += p[(size_t)(blk + 1) * DR];
            a2 += p[(size_t)(blk + 2) * DR];
            a3 += p[(size_t)(blk + 3) * DR];
        }
        sx[o] = (a0 + a1) + (a2 + a3);
    }
    __syncthreads();
    if (t < 64) sc[t] = (spart[t] + spart[t + 64]) + (spart[t + 128] + spart[t + 192]);
    __syncthreads();

    // t1 = bases @ ctc (full K range, replicated per block; pads -> 0 since bases pads are 0)
    const float* bs = g_bases + b * KPR;
    for (int idx = t; idx < KP * Rr; idx += 256) {
        int k = idx >> 3, r = idx & 7;
        float a = 0.f;
        #pragma unroll
        for (int s = 0; s < 8; s++) a = fmaf(bs[k * 8 + s], sc[s * 8 + r], a);
        st1[idx] = a;
    }
    __syncthreads();

    // bases update (glueB body)
    int idx = blockIdx.x * 256 + t;
    if (idx >= KR) return;
    int k = idx >> 3, r = idx & 7;
    const float4* et = (const float4*)(g_Et + k * Dd);
    float n0 = 0.f, n1 = 0.f, n2 = 0.f, n3 = 0.f;
    #pragma unroll 8
    for (int i = 0; i < Dd / 4; i++) {
        float4 e = et[i];
        n0 = fmaf(e.x, sx[(4 * i + 0) * 8 + r], n0);
        n1 = fmaf(e.y, sx[(4 * i + 1) * 8 + r], n1);
        n2 = fmaf(e.z, sx[(4 * i + 2) * 8 + r], n2);
        n3 = fmaf(e.w, sx[(4 * i + 3) * 8 + r], n3);
    }
    float num = (n0 + n1) + (n2 + n3);
    const float4* ee = (const float4*)(g_EtE + (size_t)k * KP);
    float d0 = 0.f, d1 = 0.f, d2 = 0.f, d3 = 0.f;
    #pragma unroll 8
    for (int i = 0; i < KP / 4; i++) {
        float4 v = ee[i];
        d0 = fmaf(v.x, st1[(4 * i + 0) * 8 + r], d0);
        d1 = fmaf(v.y, st1[(4 * i + 1) * 8 + r], d1);
        d2 = fmaf(v.z, st1[(4 * i + 2) * 8 + r], d2);
        d3 = fmaf(v.w, st1[(4 * i + 3) * 8 + r], d3);
    }
    float den = (d0 + d1) + (d2 + d3);
    g_bases[b * KPR + idx] *= num / (den + EPSV);
}

// ---------------- final coef update + reconstruction, 2 columns/thread ----------------
__global__ __launch_bounds__(256) void k_final(const float* __restrict__ x,
                                               float* __restrict__ out) {
    __shared__ __align__(16) ull ebs2[Dd * Rr];
    __shared__ ull gs2[64];
    int t = threadIdx.x, blk = blockIdx.x, b = blockIdx.y;
    int n0 = blk * 512;
    for (int i = t; i < DR; i += 256) {
        float v = g_ebp[b * DR + i] + g_ebp[(Bb + b) * DR + i];
        ebs2[i] = pk2(v, v);
    }
    __syncthreads();
    if (t < 64) {
        int r = t >> 3, s = t & 7;
        const float* ef = (const float*)ebs2;
        float a = 0.f;
        #pragma unroll 8
        for (int d = 0; d < Dd; d++)
            a = fmaf(ef[(d * 8 + r) * 2], ef[(d * 8 + s) * 2], a);
        gs2[t] = pk2(a, a);
    }

    const float* xb = x + (size_t)b * DN + n0 + 2 * t;
    ull L2a[8] = {0,0,0,0,0,0,0,0};
    #pragma unroll 1
    for (int d0 = 0; d0 < Dd; d0 += 16) {
        float2 xv[16];
        #pragma unroll
        for (int i = 0; i < 16; i++) xv[i] = *(const float2*)(xb + (size_t)(d0 + i) * Nn);
        #pragma unroll
        for (int i = 0; i < 16; i++) {
            ull x2 = pk2(xv[i].x, xv[i].y);
            const ulonglong2* ep = (const ulonglong2*)(ebs2 + (d0 + i) * 8);
            ulonglong2 e0 = ep[0], e1 = ep[1], e2 = ep[2], e3 = ep[3];
            L2a[0] = fma2_(x2, e0.x, L2a[0]);
            L2a[1] = fma2_(x2, e0.y, L2a[1]);
            L2a[2] = fma2_(x2, e1.x, L2a[2]);
            L2a[3] = fma2_(x2, e1.y, L2a[3]);
            L2a[4] = fma2_(x2, e2.x, L2a[4]);
            L2a[5] = fma2_(x2, e2.y, L2a[5]);
            L2a[6] = fma2_(x2, e3.x, L2a[6]);
            L2a[7] = fma2_(x2, e3.y, L2a[7]);
        }
    }
    __syncthreads();

    float L0[8], L1[8];
    #pragma unroll
    for (int r = 0; r < 8; r++) upk2(L2a[r], L0[r], L1[r]);

    size_t cbase = ((size_t)b * Nn + n0 + 2 * t) * 8;
    const float4* cg = (const float4*)(g_coef + cbase);
    float4 a = cg[0], cA = cg[1], dV = cg[2], eV = cg[3];
    float c0[8] = {a.x, a.y, a.z, a.w, cA.x, cA.y, cA.z, cA.w};
    float c1c[8] = {dV.x, dV.y, dV.z, dV.w, eV.x, eV.y, eV.z, eV.w};

    ull cpk[8];
    #pragma unroll
    for (int s = 0; s < 8; s++) cpk[s] = pk2(c0[s], c1c[s]);
    ull c1pk[8];
    #pragma unroll
    for (int r = 0; r < 8; r++) {
        ull den2 = 0ull;
        #pragma unroll
        for (int s = 0; s < 8; s++) den2 = fma2_(cpk[s], gs2[s * 8 + r], den2);
        float dn0, dn1; upk2(den2, dn0, dn1);
        float v0 = c0[r] * L0[r] / (dn0 + EPSV);
        float v1 = c1c[r] * L1[r] / (dn1 + EPSV);
        c1pk[r] = pk2(v0, v1);
    }

    float* ob = out + (size_t)b * DN + n0 + 2 * t;
    #pragma unroll 4
    for (int d = 0; d < Dd; d++) {
        const ulonglong2* ep = (const ulonglong2*)(ebs2 + d * 8);
        ulonglong2 e0 = ep[0], e1 = ep[1], e2 = ep[2], e3 = ep[3];
        ull acc = 0ull;
        acc = fma2_(e0.x, c1pk[0], acc);
        acc = fma2_(e0.y, c1pk[1], acc);
        acc = fma2_(e1.x, c1pk[2], acc);
        acc = fma2_(e1.y, c1pk[3], acc);
        acc = fma2_(e2.x, c1pk[4], acc);
        acc = fma2_(e2.y, c1pk[5], acc);
        acc = fma2_(e3.x, c1pk[6], acc);
        acc = fma2_(e3.y, c1pk[7], acc);
        float lo, hi; upk2(acc, lo, hi);
        *(float2*)(ob + (size_t)d * Nn) = make_float2(lo, hi);
    }
}

// ---------------- launch ----------------
extern "C" void kernel_launch(void* const* d_in, const int* in_sizes, int n_in,
                              void* d_out, int out_size) {
    const float* x = (const float*)d_in[0];
    const float* binit = (const float*)d_in[1];
    float* out = (float*)d_out;

    k_init<<<Dd + Bb, 256>>>(binit);                 // 0
    k_EbG2<<<dim3(40, 2, Bb), 256>>>();              // 1
    k_EtE<<<148, 256>>>();                           // 2
    k_step<1><<<dim3(Nn / NSLAB, Bb), 256>>>(x);     // 3  <- profiled
    k_glue<<<dim3(19, Bb), 256>>>();
    k_EbG2<<<dim3(40, 2, Bb), 256>>>();

    for (int s = 1; s < 4; s++) {
        k_step<0><<<dim3(Nn / NSLAB, Bb), 256>>>(x);
        k_glue<<<dim3(19, Bb), 256>>>();
        k_EbG2<<<dim3(40, 2, Bb), 256>>>();
    }
    k_final<<<dim3(Nn / 512, Bb), 256>>>(x, out);
}

// round 17
// speedup vs baseline: 1.1419x; 1.0015x over previous
#include <cuda_runtime.h>
#include <math.h>

#define Bb   8
#define Dd   160
#define Nn   32768
#define Kk   589
#define KP   592                 // padded K (float4-aligned, pads are zero)
#define KPR  (KP * 8)            // padded bases/t1 batch stride
#define Rr   8
#define EPSV 1e-6f
#define DN   ((size_t)Dd * (size_t)Nn)
#define KR   (Kk * Rr)           // 4712
#define DR   (Dd * Rr)           // 1280
#define NSLAB 512                // fused-step n-slab
#define NXBLK 64                 // Nn / NSLAB
#define CTS2  516                // ct row stride (floats)

typedef unsigned long long ull;

// ---------------- static device scratch ----------------
__device__ float g_E    [Dd * KP];
__device__ float g_Et   [Kk * Dd];
__device__ float g_EtE  [(size_t)Kk * KP];
__device__ float g_bases[Bb * KPR];
__device__ float g_ebp  [2 * Bb * DR];              // Eb split-K partials
__device__ float g_coef [(size_t)Bb * Nn * Rr];
__device__ float g_sxc  [(size_t)Bb * NXBLK * DR];
__device__ float g_sctc [Bb * NXBLK * 64];

// ---------------- packed f32x2 helpers ----------------
__device__ __forceinline__ ull pk2(float lo, float hi) {
    ull r;
    asm("mov.b64 %0, {%1, %2};" : "=l"(r) : "f"(lo), "f"(hi));
    return r;
}
__device__ __forceinline__ void upk2(ull v, float& lo, float& hi) {
    asm("mov.b64 {%0, %1}, %2;" : "=f"(lo), "=f"(hi) : "l"(v));
}
__device__ __forceinline__ ull fma2_(ull a, ull b, ull c) {
    ull d;
    asm("fma.rn.f32x2 %0, %1, %2, %3;" : "=l"(d) : "l"(a), "l"(b), "l"(c));
    return d;
}

// ---------------- init: build E (+T) and L2-normalize bases ----------------
__global__ void k_init(const float* __restrict__ bin) {
    if (blockIdx.x < Dd) {
        int d = blockIdx.x;
        for (int k = threadIdx.x; k < KP; k += blockDim.x) {
            float v = 0.f;
            if (k < Kk) {
                if (k == 588) {
                    v = 1.0f;
                } else {
                    float sig; int n;
                    if      (k < 160) { sig = 6.0f;  n = k; }
                    else if (k < 320) { sig = 8.0f;  n = k - 160; }
                    else if (k < 400) { sig = 12.0f; n = (k - 320) * 2; }
                    else if (k < 480) { sig = 15.0f; n = (k - 400) * 2; }
                    else if (k < 534) { sig = 18.0f; n = (k - 480) * 3; }
                    else              { sig = 24.0f; n = (k - 534) * 3; }
                    float diff = (float)d - (float)n;
                    v = expf(-0.5f * (diff * diff) / (2.0f * sig * sig));
                }
            }
            g_E[d * KP + k] = v;
            if (k < Kk) g_Et[k * Dd + d] = v;
        }
    } else {
        int b = blockIdx.x - Dd;
        int r = threadIdx.x >> 5;
        int l = threadIdx.x & 31;
        float ss = 0.f;
        for (int k = l; k < Kk; k += 32) {
            float v = bin[(b * Kk + k) * Rr + r];
            ss += v * v;
        }
        #pragma unroll
        for (int o = 16; o; o >>= 1) ss += __shfl_xor_sync(0xffffffffu, ss, o);
        float nrm = fmaxf(sqrtf(ss), 1e-12f);
        for (int k = l; k < Kk; k += 32)
            g_bases[b * KPR + k * Rr + r] = bin[(b * Kk + k) * Rr + r] / nrm;
        if (threadIdx.x < KPR - KR)
            g_bases[b * KPR + KR + threadIdx.x] = 0.f;
    }
}

// ---------------- Eb partials (+ optional fused EtE blocks) ----------------
// WITH_ETE: grid (40, 2, Bb+2); z >= Bb runs the EtE body (160 slots for 148 blocks).
template<int WITH_ETE>
__global__ __launch_bounds__(256) void k_EbG2() {
    int t = threadIdx.x;
    if (WITH_ETE && blockIdx.z >= Bb) {
        __shared__ float se[Dd * 4];
        int id = (blockIdx.z - Bb) * 80 + blockIdx.y * 40 + blockIdx.x;  // 0..159
        if (id >= 148) return;
        int i0 = id * 4;
        for (int idx = t; idx < Dd * 4; idx += 256) {
            int d = idx >> 2, i = idx & 3;
            int ki = i0 + i;
            se[idx] = (ki < Kk) ? g_Et[ki * Dd + d] : 0.f;
        }
        __syncthreads();
        int j0 = t, j1 = t + 256, j2 = t + 512;
        bool has2 = (j2 < KP);
        float a0[4] = {0,0,0,0}, a1[4] = {0,0,0,0}, a2[4] = {0,0,0,0};
        #pragma unroll 4
        for (int d = 0; d < Dd; d++) {
            float e0 = g_E[d * KP + j0];
            float e1 = g_E[d * KP + j1];
            float e2 = has2 ? g_E[d * KP + j2] : 0.f;
            #pragma unroll
            for (int i = 0; i < 4; i++) {
                float s = se[d * 4 + i];
                a0[i] = fmaf(e0, s, a0[i]);
                a1[i] = fmaf(e1, s, a1[i]);
                a2[i] = fmaf(e2, s, a2[i]);
            }
        }
        #pragma unroll
        for (int i = 0; i < 4; i++) {
            int row = i0 + i;
            if (row < Kk) {
                g_EtE[(size_t)row * KP + j0] = a0[i];
                g_EtE[(size_t)row * KP + j1] = a1[i];
                if (has2) g_EtE[(size_t)row * KP + j2] = a2[i];
            }
        }
        return;
    }
    int q = blockIdx.y, b = blockIdx.z;
    int out = t >> 3, kg = t & 7;
    int idx = blockIdx.x * 32 + out;               // 0..1279
    int d = idx >> 3, r = idx & 7;
    const float* Erow = g_E + d * KP + q * 296 + kg;
    const float* brow = g_bases + b * KPR + (q * 296 + kg) * 8 + r;
    float acc0 = 0.f, acc1 = 0.f;
    #pragma unroll
    for (int i = 0; i < 36; i += 2) {
        acc0 = fmaf(Erow[8 * i],       brow[64 * i],       acc0);
        acc1 = fmaf(Erow[8 * (i + 1)], brow[64 * (i + 1)], acc1);
    }
    acc0 = fmaf(Erow[8 * 36], brow[64 * 36], acc0);
    float acc = acc0 + acc1;
    acc += __shfl_down_sync(0xffffffffu, acc, 4);
    acc += __shfl_down_sync(0xffffffffu, acc, 2);
    acc += __shfl_down_sync(0xffffffffu, acc, 1);
    if (kg == 0) g_ebp[(q * Bb + b) * DR + idx] = acc;
}

// ---------------- fused step: coef update (2 cols/thread) + x@coef + ctc ----------------
template<int INIT>
__global__ __launch_bounds__(256) void k_step(const float* __restrict__ x) {
    __shared__ __align__(16) ull ebs2[Dd * Rr];
    __shared__ ull gs2[64];
    __shared__ __align__(16) float ct[Rr * CTS2];
    int t = threadIdx.x, blk = blockIdx.x, b = blockIdx.y;
    int n0 = blk * NSLAB;

    for (int i = t; i < DR; i += 256) {
        float v = g_ebp[b * DR + i] + g_ebp[(Bb + b) * DR + i];
        ebs2[i] = pk2(v, v);
    }
    __syncthreads();
    if (t < 64) {
        int r = t >> 3, s = t & 7;
        const float* ef = (const float*)ebs2;
        float a = 0.f;
        #pragma unroll 8
        for (int d = 0; d < Dd; d++)
            a = fmaf(ef[(d * 8 + r) * 2], ef[(d * 8 + s) * 2], a);
        gs2[t] = pk2(a, a);
    }

    // ---- phase 1 ----
    const float* xb = x + (size_t)b * DN + n0 + 2 * t;
    ull L2a[8] = {0,0,0,0,0,0,0,0};
    #pragma unroll 1
    for (int d0 = 0; d0 < Dd; d0 += 16) {
        float2 xv[16];
        #pragma unroll
        for (int i = 0; i < 16; i++) xv[i] = *(const float2*)(xb + (size_t)(d0 + i) * Nn);
        #pragma unroll
        for (int i = 0; i < 16; i++) {
            ull x2 = pk2(xv[i].x, xv[i].y);
            const ulonglong2* ep = (const ulonglong2*)(ebs2 + (d0 + i) * 8);
            ulonglong2 e0 = ep[0], e1 = ep[1], e2 = ep[2], e3 = ep[3];
            L2a[0] = fma2_(x2, e0.x, L2a[0]);
            L2a[1] = fma2_(x2, e0.y, L2a[1]);
            L2a[2] = fma2_(x2, e1.x, L2a[2]);
            L2a[3] = fma2_(x2, e1.y, L2a[3]);
            L2a[4] = fma2_(x2, e2.x, L2a[4]);
            L2a[5] = fma2_(x2, e2.y, L2a[5]);
            L2a[6] = fma2_(x2, e3.x, L2a[6]);
            L2a[7] = fma2_(x2, e3.y, L2a[7]);
        }
    }
    __syncthreads();

    float L0[8], L1[8];
    #pragma unroll
    for (int r = 0; r < 8; r++) upk2(L2a[r], L0[r], L1[r]);

    size_t cbase = ((size_t)b * Nn + n0 + 2 * t) * 8;
    float c0[8], c1c[8];
    if (INIT) {
        float m0 = L0[0], m1 = L1[0];
        #pragma unroll
        for (int i = 1; i < 8; i++) { m0 = fmaxf(m0, L0[i]); m1 = fmaxf(m1, L1[i]); }
        float p0 = 0.f, p1 = 0.f;
        #pragma unroll
        for (int i = 0; i < 8; i++) {
            c0[i] = expf(L0[i] - m0); p0 += c0[i];
            c1c[i] = expf(L1[i] - m1); p1 += c1c[i];
        }
        float i0 = 1.0f / p0, i1 = 1.0f / p1;
        #pragma unroll
        for (int i = 0; i < 8; i++) { c0[i] *= i0; c1c[i] *= i1; }
    } else {
        const float4* cg = (const float4*)(g_coef + cbase);
        float4 a = cg[0], cA = cg[1], d = cg[2], e = cg[3];
        c0[0]=a.x; c0[1]=a.y; c0[2]=a.z; c0[3]=a.w;
        c0[4]=cA.x; c0[5]=cA.y; c0[6]=cA.z; c0[7]=cA.w;
        c1c[0]=d.x; c1c[1]=d.y; c1c[2]=d.z; c1c[3]=d.w;
        c1c[4]=e.x; c1c[5]=e.y; c1c[6]=e.z; c1c[7]=e.w;
    }

    ull cpk[8];
    #pragma unroll
    for (int s = 0; s < 8; s++) cpk[s] = pk2(c0[s], c1c[s]);
    float o0[8], o1[8];
    #pragma unroll
    for (int r = 0; r < 8; r++) {
        ull den2 = 0ull;
        #pragma unroll
        for (int s = 0; s < 8; s++) den2 = fma2_(cpk[s], gs2[s * 8 + r], den2);
        float dn0, dn1; upk2(den2, dn0, dn1);
        o0[r] = c0[r] * L0[r] / (dn0 + EPSV);
        o1[r] = c1c[r] * L1[r] / (dn1 + EPSV);
    }
    float4* cgw = (float4*)(g_coef + cbase);
    cgw[0] = make_float4(o0[0], o0[1], o0[2], o0[3]);
    cgw[1] = make_float4(o0[4], o0[5], o0[6], o0[7]);
    cgw[2] = make_float4(o1[0], o1[1], o1[2], o1[3]);
    cgw[3] = make_float4(o1[4], o1[5], o1[6], o1[7]);
    #pragma unroll
    for (int r = 0; r < 8; r++)
        *(float2*)(ct + r * CTS2 + 2 * t) = make_float2(o0[r], o1[r]);
    __syncthreads();

    // ---- phase 2 ----
    {
        int p  = t & 3;
        int dq = t >> 2;
        bool has2 = (dq < 32);
        const float* xs  = x + (size_t)b * DN + n0;
        const float* xr0 = xs + (size_t)dq * Nn;
        const float* xr1 = xs + (size_t)(dq + 64) * Nn;
        const float* xr2 = xs + (size_t)(has2 ? dq + 128 : dq) * Nn;
        const ull* c0p = (const ull*)(ct + (2 * p)     * CTS2);
        const ull* c1p = (const ull*)(ct + (2 * p + 1) * CTS2);

        ull aA0=0,aB0=0,aA1=0,aB1=0,aA2=0,aB2=0;
        #pragma unroll 4
        for (int n4 = 0; n4 < NSLAB / 4; n4++) {
            ulonglong2 cc0 = *(const ulonglong2*)(c0p + n4 * 2);
            ulonglong2 cc1 = *(const ulonglong2*)(c1p + n4 * 2);
            ulonglong2 x0  = *(const ulonglong2*)(xr0 + n4 * 4);
            ulonglong2 x1  = *(const ulonglong2*)(xr1 + n4 * 4);
            aA0 = fma2_(x0.x, cc0.x, aA0); aA0 = fma2_(x0.y, cc0.y, aA0);
            aB0 = fma2_(x0.x, cc1.x, aB0); aB0 = fma2_(x0.y, cc1.y, aB0);
            aA1 = fma2_(x1.x, cc0.x, aA1); aA1 = fma2_(x1.y, cc0.y, aA1);
            aB1 = fma2_(x1.x, cc1.x, aB1); aB1 = fma2_(x1.y, cc1.y, aB1);
            if (has2) {
                ulonglong2 x2 = *(const ulonglong2*)(xr2 + n4 * 4);
                aA2 = fma2_(x2.x, cc0.x, aA2); aA2 = fma2_(x2.y, cc0.y, aA2);
                aB2 = fma2_(x2.x, cc1.x, aB2); aB2 = fma2_(x2.y, cc1.y, aB2);
            }
        }
        float* outp = g_sxc + (size_t)(b * NXBLK + blk) * DR;
        float la, ha, lb, hb;
        upk2(aA0, la, ha); upk2(aB0, lb, hb);
        *(float2*)(outp + dq * 8 + 2 * p) = make_float2(la + ha, lb + hb);
        upk2(aA1, la, ha); upk2(aB1, lb, hb);
        *(float2*)(outp + (dq + 64) * 8 + 2 * p) = make_float2(la + ha, lb + hb);
        if (has2) {
            upk2(aA2, la, ha); upk2(aB2, lb, hb);
            *(float2*)(outp + (dq + 128) * 8 + 2 * p) = make_float2(la + ha, lb + hb);
        }
    }

    if (t < 64) {
        int r = t >> 3, s = t & 7;
        const ull* rp = (const ull*)(ct + r * CTS2);
        const ull* sp = (const ull*)(ct + s * CTS2);
        ull a2 = 0ull, b2 = 0ull;
        #pragma unroll 4
        for (int i = 0; i < NSLAB / 4; i++) {
            a2 = fma2_(rp[2 * i],     sp[2 * i],     a2);
            b2 = fma2_(rp[2 * i + 1], sp[2 * i + 1], b2);
        }
        float lo, hi, lo2, hi2;
        upk2(a2, lo, hi); upk2(b2, lo2, hi2);
        g_sctc[(size_t)(b * NXBLK + blk) * 64 + t] = (lo + hi) + (lo2 + hi2);
    }
}

// ---------------- merged glue: reduce partials + t1 + bases update, grid(19,B) ----------------
__global__ __launch_bounds__(256) void k_glue() {
    __shared__ float sc[64];
    __shared__ float spart[256];
    __shared__ float sx[DR];
    __shared__ __align__(16) float st1[KP * Rr];
    int b = blockIdx.y, t = threadIdx.x;

    // reduce ctc partials (NXBLK=64)
    {
        int o = t & 63, q = t >> 6;
        const float* p = g_sctc + (size_t)b * NXBLK * 64 + o;
        float acc = 0.f;
        #pragma unroll
        for (int blk = q * 16; blk < q * 16 + 16; blk++) acc += p[blk * 64];
        spart[t] = acc;
    }
    // reduce xcoef partials into smem (full DR vector, MLP-8)
    for (int o = t; o < DR; o += 256) {
        const float* p = g_sxc + (size_t)b * NXBLK * DR + o;
        float a0 = 0, a1 = 0, a2 = 0, a3 = 0, a4 = 0, a5 = 0, a6 = 0, a7 = 0;
        #pragma unroll 2
        for (int blk = 0; blk < NXBLK; blk += 8) {
            a0 += p[(size_t)(blk + 0) * DR];
            a1 += p[(size_t)(blk + 1) * DR];
            a2 += p[(size_t)(blk + 2) * DR];
            a3 += p[(size_t)(blk + 3) * DR];
            a4 += p[(size_t)(blk + 4) * DR];
            a5 += p[(size_t)(blk + 5) * DR];
            a6 += p[(size_t)(blk + 6) * DR];
            a7 += p[(size_t)(blk + 7) * DR];
        }
        sx[o] = ((a0 + a1) + (a2 + a3)) + ((a4 + a5) + (a6 + a7));
    }
    __syncthreads();
    if (t < 64) sc[t] = (spart[t] + spart[t + 64]) + (spart[t + 128] + spart[t + 192]);
    __syncthreads();

    // t1 = bases @ ctc
    const float* bs = g_bases + b * KPR;
    for (int idx = t; idx < KP * Rr; idx += 256) {
        int k = idx >> 3, r = idx & 7;
        float a = 0.f;
        #pragma unroll
        for (int s = 0; s < 8; s++) a = fmaf(bs[k * 8 + s], sc[s * 8 + r], a);
        st1[idx] = a;
    }
    __syncthreads();

    // bases update
    int idx = blockIdx.x * 256 + t;
    if (idx >= KR) return;
    int k = idx >> 3, r = idx & 7;
    const float4* et = (const float4*)(g_Et + k * Dd);
    float n0 = 0.f, n1 = 0.f, n2 = 0.f, n3 = 0.f;
    #pragma unroll 8
    for (int i = 0; i < Dd / 4; i++) {
        float4 e = et[i];
        n0 = fmaf(e.x, sx[(4 * i + 0) * 8 + r], n0);
        n1 = fmaf(e.y, sx[(4 * i + 1) * 8 + r], n1);
        n2 = fmaf(e.z, sx[(4 * i + 2) * 8 + r], n2);
        n3 = fmaf(e.w, sx[(4 * i + 3) * 8 + r], n3);
    }
    float num = (n0 + n1) + (n2 + n3);
    const float4* ee = (const float4*)(g_EtE + (size_t)k * KP);
    float d0 = 0.f, d1 = 0.f, d2 = 0.f, d3 = 0.f;
    #pragma unroll 8
    for (int i = 0; i < KP / 4; i++) {
        float4 v = ee[i];
        d0 = fmaf(v.x, st1[(4 * i + 0) * 8 + r], d0);
        d1 = fmaf(v.y, st1[(4 * i + 1) * 8 + r], d1);
        d2 = fmaf(v.z, st1[(4 * i + 2) * 8 + r], d2);
        d3 = fmaf(v.w, st1[(4 * i + 3) * 8 + r], d3);
    }
    float den = (d0 + d1) + (d2 + d3);
    g_bases[b * KPR + idx] *= num / (den + EPSV);
}

// ---------------- final coef update + reconstruction, 2 columns/thread ----------------
__global__ __launch_bounds__(256) void k_final(const float* __restrict__ x,
                                               float* __restrict__ out) {
    __shared__ __align__(16) ull ebs2[Dd * Rr];
    __shared__ ull gs2[64];
    int t = threadIdx.x, blk = blockIdx.x, b = blockIdx.y;
    int n0 = blk * 512;
    for (int i = t; i < DR; i += 256) {
        float v = g_ebp[b * DR + i] + g_ebp[(Bb + b) * DR + i];
        ebs2[i] = pk2(v, v);
    }
    __syncthreads();
    if (t < 64) {
        int r = t >> 3, s = t & 7;
        const float* ef = (const float*)ebs2;
        float a = 0.f;
        #pragma unroll 8
        for (int d = 0; d < Dd; d++)
            a = fmaf(ef[(d * 8 + r) * 2], ef[(d * 8 + s) * 2], a);
        gs2[t] = pk2(a, a);
    }

    const float* xb = x + (size_t)b * DN + n0 + 2 * t;
    ull L2a[8] = {0,0,0,0,0,0,0,0};
    #pragma unroll 1
    for (int d0 = 0; d0 < Dd; d0 += 16) {
        float2 xv[16];
        #pragma unroll
        for (int i = 0; i < 16; i++) xv[i] = *(const float2*)(xb + (size_t)(d0 + i) * Nn);
        #pragma unroll
        for (int i = 0; i < 16; i++) {
            ull x2 = pk2(xv[i].x, xv[i].y);
            const ulonglong2* ep = (const ulonglong2*)(ebs2 + (d0 + i) * 8);
            ulonglong2 e0 = ep[0], e1 = ep[1], e2 = ep[2], e3 = ep[3];
            L2a[0] = fma2_(x2, e0.x, L2a[0]);
            L2a[1] = fma2_(x2, e0.y, L2a[1]);
            L2a[2] = fma2_(x2, e1.x, L2a[2]);
            L2a[3] = fma2_(x2, e1.y, L2a[3]);
            L2a[4] = fma2_(x2, e2.x, L2a[4]);
            L2a[5] = fma2_(x2, e2.y, L2a[5]);
            L2a[6] = fma2_(x2, e3.x, L2a[6]);
            L2a[7] = fma2_(x2, e3.y, L2a[7]);
        }
    }
    __syncthreads();

    float L0[8], L1[8];
    #pragma unroll
    for (int r = 0; r < 8; r++) upk2(L2a[r], L0[r], L1[r]);

    size_t cbase = ((size_t)b * Nn + n0 + 2 * t) * 8;
    const float4* cg = (const float4*)(g_coef + cbase);
    float4 a = cg[0], cA = cg[1], dV = cg[2], eV = cg[3];
    float c0[8] = {a.x, a.y, a.z, a.w, cA.x, cA.y, cA.z, cA.w};
    float c1c[8] = {dV.x, dV.y, dV.z, dV.w, eV.x, eV.y, eV.z, eV.w};

    ull cpk[8];
    #pragma unroll
    for (int s = 0; s < 8; s++) cpk[s] = pk2(c0[s], c1c[s]);
    ull c1pk[8];
    #pragma unroll
    for (int r = 0; r < 8; r++) {
        ull den2 = 0ull;
        #pragma unroll
        for (int s = 0; s < 8; s++) den2 = fma2_(cpk[s], gs2[s * 8 + r], den2);
        float dn0, dn1; upk2(den2, dn0, dn1);
        float v0 = c0[r] * L0[r] / (dn0 + EPSV);
        float v1 = c1c[r] * L1[r] / (dn1 + EPSV);
        c1pk[r] = pk2(v0, v1);
    }

    float* ob = out + (size_t)b * DN + n0 + 2 * t;
    #pragma unroll 4
    for (int d = 0; d < Dd; d++) {
        const ulonglong2* ep = (const ulonglong2*)(ebs2 + d * 8);
        ulonglong2 e0 = ep[0], e1 = ep[1], e2 = ep[2], e3 = ep[3];
        ull acc = 0ull;
        acc = fma2_(e0.x, c1pk[0], acc);
        acc = fma2_(e0.y, c1pk[1], acc);
        acc = fma2_(e1.x, c1pk[2], acc);
        acc = fma2_(e1.y, c1pk[3], acc);
        acc = fma2_(e2.x, c1pk[4], acc);
        acc = fma2_(e2.y, c1pk[5], acc);
        acc = fma2_(e3.x, c1pk[6], acc);
        acc = fma2_(e3.y, c1pk[7], acc);
        float lo, hi; upk2(acc, lo, hi);
        *(float2*)(ob + (size_t)d * Nn) = make_float2(lo, hi);
    }
}

// ---------------- launch ----------------
extern "C" void kernel_launch(void* const* d_in, const int* in_sizes, int n_in,
                              void* d_out, int out_size) {
    const float* x = (const float*)d_in[0];
    const float* binit = (const float*)d_in[1];
    float* out = (float*)d_out;

    k_init<<<Dd + Bb, 256>>>(binit);                      // 0
    k_EbG2<1><<<dim3(40, 2, Bb + 2), 256>>>();            // 1 (Eb + EtE fused)
    k_step<1><<<dim3(Nn / NSLAB, Bb), 256>>>(x);          // 2
    k_glue<<<dim3(19, Bb), 256>>>();                      // 3  <- profiled
    k_EbG2<0><<<dim3(40, 2, Bb), 256>>>();

    for (int s = 1; s < 4; s++) {
        k_step<0><<<dim3(Nn / NSLAB, Bb), 256>>>(x);
        k_glue<<<dim3(19, Bb), 256>>>();
        k_EbG2<0><<<dim3(40, 2, Bb), 256>>>();
    }
    k_final<<<dim3(Nn / 512, Bb), 256>>>(x, out);
}